// round 2
// baseline (speedup 1.0000x reference)
#include <cuda_runtime.h>

#define NN   50000
#define NE   800000
#define NEP  850000          // NE + NN self loops
#define FDIM 128             // HEADS*HID
#define NHEADS 4
#define FOUT 16
#define NEG  0.2f

// ---------------- scratch (static device allocations) ----------------
__device__ __align__(16) float g_bufA[NN * FDIM];   // GEMM output h (scatter source)
__device__ __align__(16) float g_bufB[NN * FDIM];   // layer output (scatter dest)
__device__ __align__(16) float g_h3[NN * FOUT];
__device__ __align__(16) float g_es[NN * NHEADS];
__device__ __align__(16) float g_ed[NN * NHEADS];
__device__ __align__(16) float g_m[NN * NHEADS];
__device__ __align__(16) float g_den[NN * NHEADS];
__device__ __align__(16) float g_pe[NEP * NHEADS];  // per-edge e / p values
__device__ int   g_src[NE];
__device__ int   g_dst[NE];
__device__ int   g_is32;                            // 1 if edge_index is int32

__device__ __forceinline__ void atomicMaxF(float* addr, float v) {
    if (v >= 0.f) atomicMax((int*)addr, __float_as_int(v));
    else          atomicMin((unsigned int*)addr, __float_as_uint(v));
}

// ---------------- dtype probe: int64 data (values < 2^31) has zero odd words ----
__global__ void k_detect(const int* __restrict__ ei) {
    if (threadIdx.x == 0) g_is32 = 0;
    __syncthreads();
    // check first 64 odd 32-bit words; any nonzero => int32 layout
    if (ei[2 * threadIdx.x + 1] != 0) atomicExch(&g_is32, 1);
}

// ---------------- edge index -> int32 src/dst ----------------
__global__ void k_convert(const int* __restrict__ ei) {
    int e = blockIdx.x * blockDim.x + threadIdx.x;
    if (e >= NE) return;
    if (g_is32) {
        g_src[e] = ei[e];
        g_dst[e] = ei[NE + e];
    } else {
        const long long* ell = (const long long*)ei;
        g_src[e] = (int)ell[e];
        g_dst[e] = (int)ell[NE + e];
    }
}

// ---------------- tiled SGEMM: C[M,Nc] = A[M,K] @ W[K,Nc] ----------------
template<int BM, int BN, int BK>
__global__ void k_gemm(const float* __restrict__ A, const float* __restrict__ W,
                       float* __restrict__ C, int M, int Nc, int K)
{
    __shared__ float As[BK][BM];
    __shared__ float Bs[BK][BN];
    const int tid = threadIdx.x;            // 256 threads
    const int tx = tid & 15, ty = tid >> 4;
    const int rowBase = blockIdx.y * BM;
    const int colBase = blockIdx.x * BN;

    float acc[4][4];
#pragma unroll
    for (int i = 0; i < 4; i++)
#pragma unroll
        for (int j = 0; j < 4; j++) acc[i][j] = 0.f;

    for (int k0 = 0; k0 < K; k0 += BK) {
#pragma unroll
        for (int i = 0; i < (BM * BK) / 256; i++) {
            int elem = tid + i * 256;
            int r = elem / BK, k = elem % BK;
            int gr = rowBase + r;
            As[k][r] = (gr < M) ? A[gr * K + k0 + k] : 0.f;
        }
#pragma unroll
        for (int i = 0; i < (BK * BN) / 256; i++) {
            int elem = tid + i * 256;
            int k = elem / BN, c = elem % BN;
            int gc = colBase + c;
            Bs[k][c] = (gc < Nc) ? W[(k0 + k) * Nc + gc] : 0.f;
        }
        __syncthreads();
#pragma unroll
        for (int k = 0; k < BK; k++) {
            float4 a = *(const float4*)&As[k][ty * 4];
            float4 b = *(const float4*)&Bs[k][tx * 4];
            float av[4] = {a.x, a.y, a.z, a.w};
            float bv[4] = {b.x, b.y, b.z, b.w};
#pragma unroll
            for (int i = 0; i < 4; i++)
#pragma unroll
                for (int j = 0; j < 4; j++) acc[i][j] += av[i] * bv[j];
        }
        __syncthreads();
    }
#pragma unroll
    for (int i = 0; i < 4; i++) {
        int gr = rowBase + ty * 4 + i;
        if (gr >= M) continue;
#pragma unroll
        for (int j = 0; j < 4; j++) {
            int gc = colBase + tx * 4 + j;
            if (gc < Nc) C[gr * Nc + gc] = acc[i][j];
        }
    }
}

// ---------------- per-node attention coefficients ----------------
template<int H, int C>
__global__ void k_attn(const float* __restrict__ h, const float* __restrict__ a_s,
                       const float* __restrict__ a_d)
{
    int i = blockIdx.x * blockDim.x + threadIdx.x;   // n*H + hh
    if (i >= NN * H) return;
    int n = i / H, hh = i % H;
    const float* hp = h + n * (H * C) + hh * C;
    float s = 0.f, d = 0.f;
#pragma unroll
    for (int c = 0; c < C; c += 4) {
        float4 hv = *(const float4*)(hp + c);
        float4 u  = *(const float4*)(a_s + hh * C + c);
        float4 v  = *(const float4*)(a_d + hh * C + c);
        s += hv.x * u.x + hv.y * u.y + hv.z * u.z + hv.w * u.w;
        d += hv.x * v.x + hv.y * v.y + hv.z * v.z + hv.w * v.w;
    }
    g_es[i] = s;
    g_ed[i] = d;
}

template<int H>
__global__ void k_init_md() {
    int i = blockIdx.x * blockDim.x + threadIdx.x;
    if (i < NN * H) {
        g_m[i] = __int_as_float(0xff800000);   // -inf
        g_den[i] = 0.f;
    }
}

// ---------------- edge pass A: e = lrelu(es[src]+ed[dst]); segment max ----------------
template<int H>
__global__ void k_edgeA() {
    int e = blockIdx.x * blockDim.x + threadIdx.x;
    if (e >= NEP) return;
    int s, d;
    if (e < NE) { s = g_src[e]; d = g_dst[e]; } else { s = e - NE; d = s; }
#pragma unroll
    for (int hh = 0; hh < H; hh++) {
        float v = g_es[s * H + hh] + g_ed[d * H + hh];
        v = (v > 0.f) ? v : NEG * v;
        g_pe[e * H + hh] = v;
        atomicMaxF(&g_m[d * H + hh], v);
    }
}

// ---------------- edge pass B: p = exp(e - m[dst]); segment sum ----------------
template<int H>
__global__ void k_edgeB() {
    int e = blockIdx.x * blockDim.x + threadIdx.x;
    if (e >= NEP) return;
    int d;
    if (e < NE) { d = g_dst[e]; } else { d = e - NE; }
#pragma unroll
    for (int hh = 0; hh < H; hh++) {
        float p = __expf(g_pe[e * H + hh] - g_m[d * H + hh]);
        g_pe[e * H + hh] = p;
        atomicAdd(&g_den[d * H + hh], p);
    }
}

// ---------------- out init to bias ----------------
__global__ void k_init_bias(float* __restrict__ o, const float* __restrict__ b,
                            int Fc, int total) {
    int i = blockIdx.x * blockDim.x + threadIdx.x;
    if (i < total) o[i] = b[i % Fc];
}

// ---------------- edge pass C (F=128): warp per edge, red.v4 scatter ----------------
__global__ void k_edgeC128(const float* __restrict__ h, float* __restrict__ o) {
    int g = blockIdx.x * blockDim.x + threadIdx.x;
    int e = g >> 5, lane = g & 31;
    if (e >= NEP) return;
    int s, d;
    if (e < NE) { s = g_src[e]; d = g_dst[e]; } else { s = e - NE; d = s; }
    int head = lane >> 3;                       // 32 ch per head, 8 lanes/head
    float alpha = g_pe[e * 4 + head] / (g_den[d * 4 + head] + 1e-16f);
    float4 hv = *(const float4*)(h + s * FDIM + lane * 4);
    float* op = o + d * FDIM + lane * 4;
    asm volatile("red.global.add.v4.f32 [%0], {%1,%2,%3,%4};"
                 :: "l"(op), "f"(alpha * hv.x), "f"(alpha * hv.y),
                    "f"(alpha * hv.z), "f"(alpha * hv.w) : "memory");
}

// ---------------- edge pass C (F=16, H=1): 4 lanes per edge ----------------
__global__ void k_edgeC16(const float* __restrict__ h, float* __restrict__ o) {
    int g = blockIdx.x * blockDim.x + threadIdx.x;
    int e = g >> 2, q = g & 3;
    if (e >= NEP) return;
    int s, d;
    if (e < NE) { s = g_src[e]; d = g_dst[e]; } else { s = e - NE; d = s; }
    float alpha = g_pe[e] / (g_den[d] + 1e-16f);
    float4 hv = *(const float4*)(h + s * FOUT + q * 4);
    float* op = o + d * FOUT + q * 4;
    asm volatile("red.global.add.v4.f32 [%0], {%1,%2,%3,%4};"
                 :: "l"(op), "f"(alpha * hv.x), "f"(alpha * hv.y),
                    "f"(alpha * hv.z), "f"(alpha * hv.w) : "memory");
}

__global__ void k_relu(float* __restrict__ p, int n) {
    int i = blockIdx.x * blockDim.x + threadIdx.x;
    if (i < n) { float v = p[i]; p[i] = v > 0.f ? v : 0.f; }
}

// ---------------- launch ----------------
extern "C" void kernel_launch(void* const* d_in, const int* in_sizes, int n_in,
                              void* d_out, int out_size)
{
    const float* x   = (const float*)d_in[0];
    const int*   ei  = (const int*)d_in[1];
    const float* W1  = (const float*)d_in[2];
    const float* as1 = (const float*)d_in[3];
    const float* ad1 = (const float*)d_in[4];
    const float* b1  = (const float*)d_in[5];
    const float* W2  = (const float*)d_in[6];
    const float* as2 = (const float*)d_in[7];
    const float* ad2 = (const float*)d_in[8];
    const float* b2  = (const float*)d_in[9];
    const float* W3  = (const float*)d_in[10];
    const float* as3 = (const float*)d_in[11];
    const float* ad3 = (const float*)d_in[12];
    const float* b3  = (const float*)d_in[13];
    float* out = (float*)d_out;

    float *bufA, *bufB, *h3;
    cudaGetSymbolAddress((void**)&bufA, g_bufA);
    cudaGetSymbolAddress((void**)&bufB, g_bufB);
    cudaGetSymbolAddress((void**)&h3,   g_h3);

    const int T = 256;
    k_detect<<<1, 64>>>(ei);
    k_convert<<<(NE + T - 1) / T, T>>>(ei);

    dim3 gBig((FDIM + 63) / 64, (NN + 63) / 64);
    dim3 gSmall(1, (NN + 63) / 64);

    // ---------- layer 1 ----------
    k_gemm<64, 64, 16><<<gBig, T>>>(x, W1, bufA, NN, FDIM, 128);
    k_attn<4, 32><<<(NN * 4 + T - 1) / T, T>>>(bufA, as1, ad1);
    k_init_md<4><<<(NN * 4 + T - 1) / T, T>>>();
    k_edgeA<4><<<(NEP + T - 1) / T, T>>>();
    k_edgeB<4><<<(NEP + T - 1) / T, T>>>();
    k_init_bias<<<(NN * FDIM + T - 1) / T, T>>>(bufB, b1, FDIM, NN * FDIM);
    k_edgeC128<<<(NEP * 32 + T - 1) / T, T>>>(bufA, bufB);
    k_relu<<<(NN * FDIM + T - 1) / T, T>>>(bufB, NN * FDIM);

    // ---------- layer 2 ----------
    k_gemm<64, 64, 16><<<gBig, T>>>(bufB, W2, bufA, NN, FDIM, FDIM);
    k_attn<4, 32><<<(NN * 4 + T - 1) / T, T>>>(bufA, as2, ad2);
    k_init_md<4><<<(NN * 4 + T - 1) / T, T>>>();
    k_edgeA<4><<<(NEP + T - 1) / T, T>>>();
    k_edgeB<4><<<(NEP + T - 1) / T, T>>>();
    k_init_bias<<<(NN * FDIM + T - 1) / T, T>>>(bufB, b2, FDIM, NN * FDIM);
    k_edgeC128<<<(NEP * 32 + T - 1) / T, T>>>(bufA, bufB);
    k_relu<<<(NN * FDIM + T - 1) / T, T>>>(bufB, NN * FDIM);

    // ---------- layer 3 (H=1, OUT=16) ----------
    k_gemm<64, 64, 16><<<gSmall, T>>>(bufB, W3, h3, NN, FOUT, FDIM);
    k_attn<1, 16><<<(NN + T - 1) / T, T>>>(h3, as3, ad3);
    k_init_md<1><<<(NN + T - 1) / T, T>>>();
    k_edgeA<1><<<(NEP + T - 1) / T, T>>>();
    k_edgeB<1><<<(NEP + T - 1) / T, T>>>();
    k_init_bias<<<(NN * FOUT + T - 1) / T, T>>>(out, b3, FOUT, NN * FOUT);
    k_edgeC16<<<(NEP * 4 + T - 1) / T, T>>>(h3, out);
}

// round 3
// speedup vs baseline: 1.4629x; 1.4629x over previous
#include <cuda_runtime.h>

#define NN   50000
#define NE   800000
#define NEP  850000          // NE + NN self loops
#define FDIM 128             // HEADS*HID
#define FOUT 16
#define NEG  0.2f

// ---------------- scratch (static device allocations) ----------------
__device__ __align__(16) float g_bufA[NN * FDIM];   // GEMM output h (scatter source)
__device__ __align__(16) float g_bufB[NN * FDIM];   // layer output (scatter dest)
__device__ __align__(16) float g_h3[NN * FOUT];
__device__ __align__(16) float g_es[NN * 4];
__device__ __align__(16) float g_ed[NN * 4];
__device__ __align__(16) float g_den[NN * 4];
__device__ __align__(16) float g_pe[NEP * 4];       // per-edge p values
__device__ int   g_src[NE];
__device__ int   g_dst[NE];
__device__ int   g_is32;

// ---------------- dtype probe: int64 data (values < 2^31) has zero odd words ----
__global__ void k_detect(const int* __restrict__ ei) {
    if (threadIdx.x == 0) g_is32 = 0;
    __syncthreads();
    if (ei[2 * threadIdx.x + 1] != 0) atomicExch(&g_is32, 1);
}

__global__ void k_convert(const int* __restrict__ ei) {
    int e = blockIdx.x * blockDim.x + threadIdx.x;
    if (e >= NE) return;
    if (g_is32) {
        g_src[e] = ei[e];
        g_dst[e] = ei[NE + e];
    } else {
        const long long* ell = (const long long*)ei;
        g_src[e] = (int)ell[e];
        g_dst[e] = (int)ell[NE + e];
    }
}

// ---------------- SGEMM 128x128x8, 8x8 microtile: C[M,128] = (relu?)A[M,128] @ W[128,128]
template<bool RELU_A>
__global__ __launch_bounds__(256) void k_gemm128(
    const float* __restrict__ A, const float* __restrict__ W,
    float* __restrict__ C, int M)
{
    __shared__ float As[8][128];
    __shared__ float Bs[8][128];
    const int tid = threadIdx.x;
    const int rowBase = blockIdx.x * 128;
    const int tx = tid & 15, ty = tid >> 4;
    const int arow = tid >> 1, apart = (tid & 1) * 4;
    const int brow = tid >> 5, bcol = (tid & 31) * 4;

    float acc[8][8];
#pragma unroll
    for (int i = 0; i < 8; i++)
#pragma unroll
        for (int j = 0; j < 8; j++) acc[i][j] = 0.f;

    const int gr = rowBase + arow;
    const float* Ap = A + (long)gr * 128 + apart;

    for (int k0 = 0; k0 < 128; k0 += 8) {
        float4 av = (gr < M) ? *(const float4*)(Ap + k0) : make_float4(0, 0, 0, 0);
        if (RELU_A) {
            av.x = fmaxf(av.x, 0.f); av.y = fmaxf(av.y, 0.f);
            av.z = fmaxf(av.z, 0.f); av.w = fmaxf(av.w, 0.f);
        }
        As[apart + 0][arow] = av.x;
        As[apart + 1][arow] = av.y;
        As[apart + 2][arow] = av.z;
        As[apart + 3][arow] = av.w;
        *(float4*)&Bs[brow][bcol] = *(const float4*)(W + (k0 + brow) * 128 + bcol);
        __syncthreads();
#pragma unroll
        for (int k = 0; k < 8; k++) {
            float a[8], b[8];
            *(float4*)(a)     = *(const float4*)&As[k][ty * 8];
            *(float4*)(a + 4) = *(const float4*)&As[k][ty * 8 + 4];
            *(float4*)(b)     = *(const float4*)&Bs[k][tx * 8];
            *(float4*)(b + 4) = *(const float4*)&Bs[k][tx * 8 + 4];
#pragma unroll
            for (int i = 0; i < 8; i++)
#pragma unroll
                for (int j = 0; j < 8; j++) acc[i][j] += a[i] * b[j];
        }
        __syncthreads();
    }
#pragma unroll
    for (int i = 0; i < 8; i++) {
        int r = rowBase + ty * 8 + i;
        if (r >= M) break;
        float* Cp = C + (long)r * 128 + tx * 8;
        *(float4*)(Cp)     = make_float4(acc[i][0], acc[i][1], acc[i][2], acc[i][3]);
        *(float4*)(Cp + 4) = make_float4(acc[i][4], acc[i][5], acc[i][6], acc[i][7]);
    }
}

// ---------------- layer-3 GEMM: C[M,16] = relu(A)[M,128] @ W[128,16] ----------------
__global__ __launch_bounds__(256) void k_gemm16(
    const float* __restrict__ A, const float* __restrict__ W,
    float* __restrict__ C, int M)
{
    __shared__ float Ws[128 * 16];
    int tid = threadIdx.x;
    for (int i = tid * 4; i < 2048; i += 1024)
        *(float4*)&Ws[i] = *(const float4*)(W + i);
    __syncthreads();
    int row = blockIdx.x * 64 + (tid >> 2);
    int c4 = (tid & 3) * 4;
    if (row >= M) return;
    const float* Ap = A + (long)row * 128;
    float4 acc = make_float4(0, 0, 0, 0);
#pragma unroll 8
    for (int k = 0; k < 128; k += 4) {
        float4 a = *(const float4*)(Ap + k);
        a.x = fmaxf(a.x, 0.f); a.y = fmaxf(a.y, 0.f);
        a.z = fmaxf(a.z, 0.f); a.w = fmaxf(a.w, 0.f);
#pragma unroll
        for (int kk = 0; kk < 4; kk++) {
            float av = (&a.x)[kk];
            float4 w = *(const float4*)&Ws[(k + kk) * 16 + c4];
            acc.x += av * w.x; acc.y += av * w.y;
            acc.z += av * w.z; acc.w += av * w.w;
        }
    }
    *(float4*)(C + (long)row * 16 + c4) = acc;
}

// ---------------- per-node attention coefficients (+den init) ----------------
template<int H, int C>
__global__ void k_attn(const float* __restrict__ h, const float* __restrict__ a_s,
                       const float* __restrict__ a_d)
{
    int i = blockIdx.x * blockDim.x + threadIdx.x;   // n*H + hh
    if (i >= NN * H) return;
    int n = i / H, hh = i % H;
    const float* hp = h + (long)n * (H * C) + hh * C;
    float s = 0.f, d = 0.f;
#pragma unroll
    for (int c = 0; c < C; c += 4) {
        float4 hv = *(const float4*)(hp + c);
        float4 u  = *(const float4*)(a_s + hh * C + c);
        float4 v  = *(const float4*)(a_d + hh * C + c);
        s += hv.x * u.x + hv.y * u.y + hv.z * u.z + hv.w * u.w;
        d += hv.x * v.x + hv.y * v.y + hv.z * v.z + hv.w * v.w;
    }
    g_es[i] = s;
    g_ed[i] = d;
    g_den[i] = 0.f;
}

// ---------------- fused edge pass: p = exp(lrelu(es[src]+ed[dst])); den += p ----
__global__ void k_edgeAB4() {
    int e = blockIdx.x * blockDim.x + threadIdx.x;
    if (e >= NEP) return;
    int s, d;
    if (e < NE) { s = g_src[e]; d = g_dst[e]; } else { s = e - NE; d = s; }
    float4 es = *(const float4*)(g_es + s * 4);
    float4 ed = *(const float4*)(g_ed + d * 4);
    float4 p;
    float v;
    v = es.x + ed.x; v = (v > 0.f) ? v : NEG * v; p.x = __expf(v);
    v = es.y + ed.y; v = (v > 0.f) ? v : NEG * v; p.y = __expf(v);
    v = es.z + ed.z; v = (v > 0.f) ? v : NEG * v; p.z = __expf(v);
    v = es.w + ed.w; v = (v > 0.f) ? v : NEG * v; p.w = __expf(v);
    *(float4*)(g_pe + e * 4) = p;
    asm volatile("red.global.add.v4.f32 [%0], {%1,%2,%3,%4};"
                 :: "l"(g_den + d * 4), "f"(p.x), "f"(p.y), "f"(p.z), "f"(p.w)
                 : "memory");
}

__global__ void k_edgeAB1() {
    int e = blockIdx.x * blockDim.x + threadIdx.x;
    if (e >= NEP) return;
    int s, d;
    if (e < NE) { s = g_src[e]; d = g_dst[e]; } else { s = e - NE; d = s; }
    float v = g_es[s] + g_ed[d];
    v = (v > 0.f) ? v : NEG * v;
    float p = __expf(v);
    g_pe[e] = p;
    atomicAdd(&g_den[d], p);
}

// ---------------- out init to bias (vectorized) ----------------
__global__ void k_init_bias(float* __restrict__ o, const float* __restrict__ b,
                            int Fc4, int total4) {
    int i = blockIdx.x * blockDim.x + threadIdx.x;
    if (i < total4)
        ((float4*)o)[i] = ((const float4*)b)[i % Fc4];
}

// ---------------- scatter (F=128): warp per edge, red.v4 ----------------
__global__ void k_edgeC128(const float* __restrict__ h, float* __restrict__ o) {
    int g = blockIdx.x * blockDim.x + threadIdx.x;
    int e = g >> 5, lane = g & 31;
    if (e >= NEP) return;
    int s, d;
    if (e < NE) { s = g_src[e]; d = g_dst[e]; } else { s = e - NE; d = s; }
    int head = lane >> 3;
    float alpha = g_pe[e * 4 + head] / (g_den[d * 4 + head] + 1e-16f);
    float4 hv = *(const float4*)(h + (long)s * FDIM + lane * 4);
    float* op = o + (long)d * FDIM + lane * 4;
    asm volatile("red.global.add.v4.f32 [%0], {%1,%2,%3,%4};"
                 :: "l"(op), "f"(alpha * hv.x), "f"(alpha * hv.y),
                    "f"(alpha * hv.z), "f"(alpha * hv.w) : "memory");
}

// ---------------- scatter (F=16, H=1): 4 lanes per edge ----------------
__global__ void k_edgeC16(const float* __restrict__ h, float* __restrict__ o) {
    int g = blockIdx.x * blockDim.x + threadIdx.x;
    int e = g >> 2, q = g & 3;
    if (e >= NEP) return;
    int s, d;
    if (e < NE) { s = g_src[e]; d = g_dst[e]; } else { s = e - NE; d = s; }
    float alpha = g_pe[e] / (g_den[d] + 1e-16f);
    float4 hv = *(const float4*)(h + (long)s * FOUT + q * 4);
    float* op = o + (long)d * FOUT + q * 4;
    asm volatile("red.global.add.v4.f32 [%0], {%1,%2,%3,%4};"
                 :: "l"(op), "f"(alpha * hv.x), "f"(alpha * hv.y),
                    "f"(alpha * hv.z), "f"(alpha * hv.w) : "memory");
}

// ---------------- launch ----------------
extern "C" void kernel_launch(void* const* d_in, const int* in_sizes, int n_in,
                              void* d_out, int out_size)
{
    const float* x   = (const float*)d_in[0];
    const int*   ei  = (const int*)d_in[1];
    const float* W1  = (const float*)d_in[2];
    const float* as1 = (const float*)d_in[3];
    const float* ad1 = (const float*)d_in[4];
    const float* b1  = (const float*)d_in[5];
    const float* W2  = (const float*)d_in[6];
    const float* as2 = (const float*)d_in[7];
    const float* ad2 = (const float*)d_in[8];
    const float* b2  = (const float*)d_in[9];
    const float* W3  = (const float*)d_in[10];
    const float* as3 = (const float*)d_in[11];
    const float* ad3 = (const float*)d_in[12];
    const float* b3  = (const float*)d_in[13];
    float* out = (float*)d_out;

    float *bufA, *bufB, *h3;
    cudaGetSymbolAddress((void**)&bufA, g_bufA);
    cudaGetSymbolAddress((void**)&bufB, g_bufB);
    cudaGetSymbolAddress((void**)&h3,   g_h3);

    const int T = 256;
    k_detect<<<1, 64>>>(ei);
    k_convert<<<(NE + T - 1) / T, T>>>(ei);

    const int gGemm = (NN + 127) / 128;

    // ---------- layer 1 ----------
    k_gemm128<false><<<gGemm, T>>>(x, W1, bufA, NN);
    k_attn<4, 32><<<(NN * 4 + T - 1) / T, T>>>(bufA, as1, ad1);
    k_edgeAB4<<<(NEP + T - 1) / T, T>>>();
    k_init_bias<<<(NN * 32 + T - 1) / T, T>>>(bufB, b1, 32, NN * 32);
    k_edgeC128<<<(NEP * 32 + T - 1) / T, T>>>(bufA, bufB);

    // ---------- layer 2 (ReLU fused into A-load) ----------
    k_gemm128<true><<<gGemm, T>>>(bufB, W2, bufA, NN);
    k_attn<4, 32><<<(NN * 4 + T - 1) / T, T>>>(bufA, as2, ad2);
    k_edgeAB4<<<(NEP + T - 1) / T, T>>>();
    k_init_bias<<<(NN * 32 + T - 1) / T, T>>>(bufB, b2, 32, NN * 32);
    k_edgeC128<<<(NEP * 32 + T - 1) / T, T>>>(bufA, bufB);

    // ---------- layer 3 (H=1, OUT=16; ReLU fused) ----------
    k_gemm16<<<(NN + 63) / 64, T>>>(bufB, W3, h3, NN);
    k_attn<1, 16><<<(NN + T - 1) / T, T>>>(h3, as3, ad3);
    k_edgeAB1<<<(NEP + T - 1) / T, T>>>();
    k_init_bias<<<(NN * 4 + T - 1) / T, T>>>(out, b3, 4, NN * 4);
    k_edgeC16<<<(NEP * 4 + T - 1) / T, T>>>(h3, out);
}

// round 4
// speedup vs baseline: 1.6698x; 1.1414x over previous
#include <cuda_runtime.h>

#define NN   50000
#define NE   800000
#define FDIM 128
#define FOUT 16
#define NEG  0.2f
#define SCAN_B 512
#define NSCANB ((NN + SCAN_B - 1) / SCAN_B)   // 98

// ---------------- scratch ----------------
__device__ __align__(16) float g_bufA[NN * FDIM];   // h = GEMM out
__device__ __align__(16) float g_bufB[NN * FDIM];   // aggregated activation
__device__ __align__(16) float g_h3[NN * FOUT];
__device__ __align__(16) float g_es[NN * 4];
__device__ __align__(16) float g_ed[NN * 4];
__device__ int g_src[NE];
__device__ int g_dst[NE];
__device__ int g_deg[NN];
__device__ int g_rowptr[NN + 1];
__device__ int g_cursor[NN];
__device__ int g_csrc[NE];
__device__ int g_bsum[128];
__device__ int g_is32;

// ---------------- edge index ingest + degree histogram ----------------
__global__ void k_detect(const int* __restrict__ ei) {
    if (threadIdx.x == 0) g_is32 = 0;
    __syncthreads();
    if (ei[2 * threadIdx.x + 1] != 0) atomicExch(&g_is32, 1);
}

__global__ void k_zero_deg() {
    int i = blockIdx.x * blockDim.x + threadIdx.x;
    if (i < NN) g_deg[i] = 0;
}

__global__ void k_convert(const int* __restrict__ ei) {
    int e = blockIdx.x * blockDim.x + threadIdx.x;
    if (e >= NE) return;
    int s, d;
    if (g_is32) {
        s = ei[e]; d = ei[NE + e];
    } else {
        const long long* ell = (const long long*)ei;
        s = (int)ell[e]; d = (int)ell[NE + e];
    }
    g_src[e] = s;
    g_dst[e] = d;
    atomicAdd(&g_deg[d], 1);
}

// ---------------- exclusive scan (3 kernels) ----------------
__global__ void k_scan1() {
    __shared__ int sm[SCAN_B];
    int i = blockIdx.x * SCAN_B + threadIdx.x;
    int v = (i < NN) ? g_deg[i] : 0;
    sm[threadIdx.x] = v;
    __syncthreads();
#pragma unroll
    for (int off = 1; off < SCAN_B; off <<= 1) {
        int t = (threadIdx.x >= off) ? sm[threadIdx.x - off] : 0;
        __syncthreads();
        sm[threadIdx.x] += t;
        __syncthreads();
    }
    if (i < NN) g_rowptr[i] = sm[threadIdx.x] - v;   // exclusive within block
    if (threadIdx.x == SCAN_B - 1) g_bsum[blockIdx.x] = sm[SCAN_B - 1];
}

__global__ void k_scan2() {
    if (threadIdx.x == 0) {
        int run = 0;
        for (int b = 0; b < NSCANB; b++) { int t = g_bsum[b]; g_bsum[b] = run; run += t; }
    }
}

__global__ void k_scan3() {
    int i = blockIdx.x * blockDim.x + threadIdx.x;
    if (i < NN) {
        int v = g_rowptr[i] + g_bsum[i / SCAN_B];
        g_rowptr[i] = v;
        g_cursor[i] = v;
    }
    if (i == 0) g_rowptr[NN] = NE;
}

__global__ void k_fill() {
    int e = blockIdx.x * blockDim.x + threadIdx.x;
    if (e >= NE) return;
    int pos = atomicAdd(&g_cursor[g_dst[e]], 1);
    g_csrc[pos] = g_src[e];
}

// ---------------- SGEMM 128x128x8, 8x8 microtile ----------------
__global__ __launch_bounds__(256) void k_gemm128(
    const float* __restrict__ A, const float* __restrict__ W,
    float* __restrict__ C, int M)
{
    __shared__ float As[8][128];
    __shared__ float Bs[8][128];
    const int tid = threadIdx.x;
    const int rowBase = blockIdx.x * 128;
    const int tx = tid & 15, ty = tid >> 4;
    const int arow = tid >> 1, apart = (tid & 1) * 4;
    const int brow = tid >> 5, bcol = (tid & 31) * 4;

    float acc[8][8];
#pragma unroll
    for (int i = 0; i < 8; i++)
#pragma unroll
        for (int j = 0; j < 8; j++) acc[i][j] = 0.f;

    const int gr = rowBase + arow;
    const float* Ap = A + (long)gr * 128 + apart;

    for (int k0 = 0; k0 < 128; k0 += 8) {
        float4 av = (gr < M) ? *(const float4*)(Ap + k0) : make_float4(0, 0, 0, 0);
        As[apart + 0][arow] = av.x;
        As[apart + 1][arow] = av.y;
        As[apart + 2][arow] = av.z;
        As[apart + 3][arow] = av.w;
        *(float4*)&Bs[brow][bcol] = *(const float4*)(W + (k0 + brow) * 128 + bcol);
        __syncthreads();
#pragma unroll
        for (int k = 0; k < 8; k++) {
            float a[8], b[8];
            *(float4*)(a)     = *(const float4*)&As[k][ty * 8];
            *(float4*)(a + 4) = *(const float4*)&As[k][ty * 8 + 4];
            *(float4*)(b)     = *(const float4*)&Bs[k][tx * 8];
            *(float4*)(b + 4) = *(const float4*)&Bs[k][tx * 8 + 4];
#pragma unroll
            for (int i = 0; i < 8; i++)
#pragma unroll
                for (int j = 0; j < 8; j++) acc[i][j] += a[i] * b[j];
        }
        __syncthreads();
    }
#pragma unroll
    for (int i = 0; i < 8; i++) {
        int r = rowBase + ty * 8 + i;
        if (r >= M) break;
        float* Cp = C + (long)r * 128 + tx * 8;
        *(float4*)(Cp)     = make_float4(acc[i][0], acc[i][1], acc[i][2], acc[i][3]);
        *(float4*)(Cp + 4) = make_float4(acc[i][4], acc[i][5], acc[i][6], acc[i][7]);
    }
}

// ---------------- layer-3 GEMM: C[M,16] = A[M,128] @ W[128,16] ----------------
__global__ __launch_bounds__(256) void k_gemm16(
    const float* __restrict__ A, const float* __restrict__ W,
    float* __restrict__ C, int M)
{
    __shared__ float Ws[128 * 16];
    int tid = threadIdx.x;
    for (int i = tid * 4; i < 2048; i += 1024)
        *(float4*)&Ws[i] = *(const float4*)(W + i);
    __syncthreads();
    int row = blockIdx.x * 64 + (tid >> 2);
    int c4 = (tid & 3) * 4;
    if (row >= M) return;
    const float* Ap = A + (long)row * 128;
    float4 acc = make_float4(0, 0, 0, 0);
#pragma unroll 8
    for (int k = 0; k < 128; k += 4) {
        float4 a = *(const float4*)(Ap + k);
#pragma unroll
        for (int kk = 0; kk < 4; kk++) {
            float av = (&a.x)[kk];
            float4 w = *(const float4*)&Ws[(k + kk) * 16 + c4];
            acc.x += av * w.x; acc.y += av * w.y;
            acc.z += av * w.z; acc.w += av * w.w;
        }
    }
    *(float4*)(C + (long)row * 16 + c4) = acc;
}

// ---------------- attn coefficients: warp per node (H=4, C=32) ----------------
__global__ void k_attn4(const float* __restrict__ h, const float* __restrict__ a_s,
                        const float* __restrict__ a_d)
{
    int w = (blockIdx.x * blockDim.x + threadIdx.x) >> 5;
    int lane = threadIdx.x & 31;
    if (w >= NN) return;
    int head = lane >> 3, part = lane & 7;
    float4 hv = *(const float4*)(h + (long)w * 128 + lane * 4);
    float4 u  = *(const float4*)(a_s + head * 32 + part * 4);
    float4 v  = *(const float4*)(a_d + head * 32 + part * 4);
    float s = hv.x * u.x + hv.y * u.y + hv.z * u.z + hv.w * u.w;
    float d = hv.x * v.x + hv.y * v.y + hv.z * v.z + hv.w * v.w;
#pragma unroll
    for (int off = 4; off > 0; off >>= 1) {
        s += __shfl_xor_sync(0xffffffff, s, off);
        d += __shfl_xor_sync(0xffffffff, d, off);
    }
    if (part == 0) {
        g_es[w * 4 + head] = s;
        g_ed[w * 4 + head] = d;
    }
}

// ---------------- attn coefficients: 4 lanes per node (H=1, C=16) ----------------
__global__ void k_attn1(const float* __restrict__ h, const float* __restrict__ a_s,
                        const float* __restrict__ a_d)
{
    int g = blockIdx.x * blockDim.x + threadIdx.x;
    int n = g >> 2, q = g & 3;
    if (n >= NN) return;
    float4 hv = *(const float4*)(h + (long)n * 16 + q * 4);
    float4 u  = *(const float4*)(a_s + q * 4);
    float4 v  = *(const float4*)(a_d + q * 4);
    float s = hv.x * u.x + hv.y * u.y + hv.z * u.z + hv.w * u.w;
    float d = hv.x * v.x + hv.y * v.y + hv.z * v.z + hv.w * v.w;
    s += __shfl_xor_sync(0xffffffff, s, 1);
    d += __shfl_xor_sync(0xffffffff, d, 1);
    s += __shfl_xor_sync(0xffffffff, s, 2);
    d += __shfl_xor_sync(0xffffffff, d, 2);
    if (q == 0) { g_es[n] = s; g_ed[n] = d; }
}

// ---------------- fused gather: softmax-weighted aggregation, warp per dst ----
template<bool RELU>
__global__ void k_gather128(const float* __restrict__ h, float* __restrict__ o,
                            const float* __restrict__ bias)
{
    int w = (blockIdx.x * blockDim.x + threadIdx.x) >> 5;
    int lane = threadIdx.x & 31;
    if (w >= NN) return;
    int head = lane >> 3;
    float edh = g_ed[w * 4 + head];
    float denom = 0.f;
    float4 acc = make_float4(0, 0, 0, 0);

    // self loop
    {
        float v = g_es[w * 4 + head] + edh;
        v = (v > 0.f) ? v : NEG * v;
        float p = __expf(v);
        denom += p;
        float4 hv = *(const float4*)(h + (long)w * 128 + lane * 4);
        acc.x += p * hv.x; acc.y += p * hv.y; acc.z += p * hv.z; acc.w += p * hv.w;
    }
    int start = g_rowptr[w], end = g_rowptr[w + 1];
    for (int j = start; j < end; j++) {
        int s = g_csrc[j];
        float v = g_es[s * 4 + head] + edh;
        v = (v > 0.f) ? v : NEG * v;
        float p = __expf(v);
        denom += p;
        float4 hv = *(const float4*)(h + (long)s * 128 + lane * 4);
        acc.x += p * hv.x; acc.y += p * hv.y; acc.z += p * hv.z; acc.w += p * hv.w;
    }
    float inv = 1.f / (denom + 1e-16f);
    float4 b = *(const float4*)(bias + lane * 4);
    float4 r;
    r.x = acc.x * inv + b.x; r.y = acc.y * inv + b.y;
    r.z = acc.z * inv + b.z; r.w = acc.w * inv + b.w;
    if (RELU) {
        r.x = fmaxf(r.x, 0.f); r.y = fmaxf(r.y, 0.f);
        r.z = fmaxf(r.z, 0.f); r.w = fmaxf(r.w, 0.f);
    }
    *(float4*)(o + (long)w * 128 + lane * 4) = r;
}

// ---------------- fused gather (F=16, H=1): 4 lanes per dst ----------------
__global__ void k_gather16(const float* __restrict__ h, float* __restrict__ o,
                           const float* __restrict__ bias)
{
    int g = blockIdx.x * blockDim.x + threadIdx.x;
    int n = g >> 2, q = g & 3;
    if (n >= NN) return;
    float edh = g_ed[n];
    float denom = 0.f;
    float4 acc = make_float4(0, 0, 0, 0);
    {
        float v = g_es[n] + edh;
        v = (v > 0.f) ? v : NEG * v;
        float p = __expf(v);
        denom += p;
        float4 hv = *(const float4*)(h + (long)n * 16 + q * 4);
        acc.x += p * hv.x; acc.y += p * hv.y; acc.z += p * hv.z; acc.w += p * hv.w;
    }
    int start = g_rowptr[n], end = g_rowptr[n + 1];
    for (int j = start; j < end; j++) {
        int s = g_csrc[j];
        float v = g_es[s] + edh;
        v = (v > 0.f) ? v : NEG * v;
        float p = __expf(v);
        denom += p;
        float4 hv = *(const float4*)(h + (long)s * 16 + q * 4);
        acc.x += p * hv.x; acc.y += p * hv.y; acc.z += p * hv.z; acc.w += p * hv.w;
    }
    float inv = 1.f / (denom + 1e-16f);
    float4 b = *(const float4*)(bias + q * 4);
    float4 r;
    r.x = acc.x * inv + b.x; r.y = acc.y * inv + b.y;
    r.z = acc.z * inv + b.z; r.w = acc.w * inv + b.w;
    *(float4*)(o + (long)n * 16 + q * 4) = r;
}

// ---------------- launch ----------------
extern "C" void kernel_launch(void* const* d_in, const int* in_sizes, int n_in,
                              void* d_out, int out_size)
{
    const float* x   = (const float*)d_in[0];
    const int*   ei  = (const int*)d_in[1];
    const float* W1  = (const float*)d_in[2];
    const float* as1 = (const float*)d_in[3];
    const float* ad1 = (const float*)d_in[4];
    const float* b1  = (const float*)d_in[5];
    const float* W2  = (const float*)d_in[6];
    const float* as2 = (const float*)d_in[7];
    const float* ad2 = (const float*)d_in[8];
    const float* b2  = (const float*)d_in[9];
    const float* W3  = (const float*)d_in[10];
    const float* as3 = (const float*)d_in[11];
    const float* ad3 = (const float*)d_in[12];
    const float* b3  = (const float*)d_in[13];
    float* out = (float*)d_out;

    float *bufA, *bufB, *h3;
    cudaGetSymbolAddress((void**)&bufA, g_bufA);
    cudaGetSymbolAddress((void**)&bufB, g_bufB);
    cudaGetSymbolAddress((void**)&h3,   g_h3);

    const int T = 256;
    // ---- CSR build (once; shared by all 3 layers) ----
    k_detect<<<1, 64>>>(ei);
    k_zero_deg<<<(NN + T - 1) / T, T>>>();
    k_convert<<<(NE + T - 1) / T, T>>>(ei);
    k_scan1<<<NSCANB, SCAN_B>>>();
    k_scan2<<<1, 32>>>();
    k_scan3<<<(NN + T - 1) / T, T>>>();
    k_fill<<<(NE + T - 1) / T, T>>>();

    const int gGemm = (NN + 127) / 128;
    const int gWarp = (NN * 32 + T - 1) / T;     // warp per node
    const int gQuad = (NN * 4 + T - 1) / T;      // 4 lanes per node

    // ---------- layer 1 ----------
    k_gemm128<<<gGemm, T>>>(x, W1, bufA, NN);
    k_attn4<<<gWarp, T>>>(bufA, as1, ad1);
    k_gather128<true><<<gWarp, T>>>(bufA, bufB, b1);

    // ---------- layer 2 ----------
    k_gemm128<<<gGemm, T>>>(bufB, W2, bufA, NN);
    k_attn4<<<gWarp, T>>>(bufA, as2, ad2);
    k_gather128<true><<<gWarp, T>>>(bufA, bufB, b2);

    // ---------- layer 3 ----------
    k_gemm16<<<(NN + 63) / 64, T>>>(bufB, W3, h3, NN);
    k_attn1<<<gQuad, T>>>(h3, as3, ad3);
    k_gather16<<<gQuad, T>>>(h3, out, b3);
}

// round 5
// speedup vs baseline: 2.4128x; 1.4449x over previous
#include <cuda_runtime.h>

#define NN   50000
#define NE   800000
#define FDIM 128
#define FOUT 16
#define NEG  0.2f
#define SCAN_B 512
#define NSCANB ((NN + SCAN_B - 1) / SCAN_B)   // 98

// ---------------- scratch ----------------
__device__ __align__(16) float g_bufA[NN * FDIM];   // h = GEMM out
__device__ __align__(16) float g_bufB[NN * FDIM];   // aggregated activation
__device__ __align__(16) float g_h3[NN * FOUT];
__device__ __align__(16) float g_es[NN * 4];
__device__ __align__(16) float g_ed[NN * 4];
__device__ int g_src[NE];
__device__ int g_dst[NE];
__device__ int g_deg[NN];
__device__ int g_rowptr[NN + 1];
__device__ int g_cursor[NN];
__device__ int g_csrc[NE];
__device__ int g_bsum[128];
__device__ int g_is32;

// ---------------- detect dtype + zero degree ----------------
__global__ void k_prep(const int* __restrict__ ei) {
    int i = blockIdx.x * blockDim.x + threadIdx.x;
    if (i == 0) g_is32 = 0;
    if (i < NN) g_deg[i] = 0;
}
__global__ void k_detect(const int* __restrict__ ei) {
    // int64 data (values < 2^31, >=0) has all-zero odd words
    if (ei[2 * threadIdx.x + 1] != 0) atomicExch(&g_is32, 1);
}

__global__ void k_convert(const int* __restrict__ ei) {
    int e = blockIdx.x * blockDim.x + threadIdx.x;
    if (e >= NE) return;
    int s, d;
    if (g_is32) {
        s = ei[e]; d = ei[NE + e];
    } else {
        const long long* ell = (const long long*)ei;
        s = (int)ell[e]; d = (int)ell[NE + e];
    }
    g_src[e] = s;
    g_dst[e] = d;
    atomicAdd(&g_deg[d], 1);
}

// ---------------- exclusive scan (2 kernels) ----------------
__global__ void k_scan1() {
    __shared__ int sm[SCAN_B];
    int i = blockIdx.x * SCAN_B + threadIdx.x;
    int v = (i < NN) ? g_deg[i] : 0;
    sm[threadIdx.x] = v;
    __syncthreads();
#pragma unroll
    for (int off = 1; off < SCAN_B; off <<= 1) {
        int t = (threadIdx.x >= off) ? sm[threadIdx.x - off] : 0;
        __syncthreads();
        sm[threadIdx.x] += t;
        __syncthreads();
    }
    if (i < NN) g_rowptr[i] = sm[threadIdx.x] - v;   // exclusive within block
    if (threadIdx.x == SCAN_B - 1) g_bsum[blockIdx.x] = sm[SCAN_B - 1];
}

__global__ void k_scan3() {
    __shared__ int pre[NSCANB];
    if (threadIdx.x < NSCANB) pre[threadIdx.x] = g_bsum[threadIdx.x];
    __syncthreads();
    if (threadIdx.x == 0) {
        int run = 0;
#pragma unroll 1
        for (int b = 0; b < NSCANB; b++) { int t = pre[b]; pre[b] = run; run += t; }
    }
    __syncthreads();
    int i = blockIdx.x * blockDim.x + threadIdx.x;
    if (i < NN) {
        int v = g_rowptr[i] + pre[i / SCAN_B];
        g_rowptr[i] = v;
        g_cursor[i] = v;
    }
    if (i == 0) g_rowptr[NN] = NE;
}

__global__ void k_fill() {
    int e = blockIdx.x * blockDim.x + threadIdx.x;
    if (e >= NE) return;
    int pos = atomicAdd(&g_cursor[g_dst[e]], 1);
    g_csrc[pos] = g_src[e];
}

// ------- SGEMM 128x128x8, 8x8 microtile, double-buffered, fused attn epilogue ----
__global__ __launch_bounds__(256) void k_gemm128(
    const float* __restrict__ A, const float* __restrict__ W,
    float* __restrict__ C, int M,
    const float* __restrict__ a_s, const float* __restrict__ a_d)
{
    __shared__ float As[8][128];
    __shared__ float Bs[8][128];
    const int tid = threadIdx.x;
    const int rowBase = blockIdx.x * 128;
    const int tx = tid & 15, ty = tid >> 4;
    const int arow = tid >> 1, apart = (tid & 1) * 4;
    const int brow = tid >> 5, bcol = (tid & 31) * 4;

    float acc[8][8];
#pragma unroll
    for (int i = 0; i < 8; i++)
#pragma unroll
        for (int j = 0; j < 8; j++) acc[i][j] = 0.f;

    const int gr = rowBase + arow;
    const float* Ap = A + (long)gr * 128 + apart;
    const float* Wp = W + brow * 128 + bcol;

    float4 av = (gr < M) ? *(const float4*)(Ap) : make_float4(0, 0, 0, 0);
    float4 bv = *(const float4*)(Wp);

    for (int k0 = 0; k0 < 128; k0 += 8) {
        As[apart + 0][arow] = av.x;
        As[apart + 1][arow] = av.y;
        As[apart + 2][arow] = av.z;
        As[apart + 3][arow] = av.w;
        *(float4*)&Bs[brow][bcol] = bv;
        __syncthreads();
        if (k0 + 8 < 128) {
            av = (gr < M) ? *(const float4*)(Ap + k0 + 8) : make_float4(0, 0, 0, 0);
            bv = *(const float4*)(Wp + (k0 + 8) * 128);
        }
#pragma unroll
        for (int k = 0; k < 8; k++) {
            float a[8], b[8];
            *(float4*)(a)     = *(const float4*)&As[k][ty * 8];
            *(float4*)(a + 4) = *(const float4*)&As[k][ty * 8 + 4];
            *(float4*)(b)     = *(const float4*)&Bs[k][tx * 8];
            *(float4*)(b + 4) = *(const float4*)&Bs[k][tx * 8 + 4];
#pragma unroll
            for (int i = 0; i < 8; i++)
#pragma unroll
                for (int j = 0; j < 8; j++) acc[i][j] += a[i] * b[j];
        }
        __syncthreads();
    }

    // ---- write C ----
#pragma unroll
    for (int i = 0; i < 8; i++) {
        int r = rowBase + ty * 8 + i;
        if (r < M) {
            float* Cp = C + (long)r * 128 + tx * 8;
            *(float4*)(Cp)     = make_float4(acc[i][0], acc[i][1], acc[i][2], acc[i][3]);
            *(float4*)(Cp + 4) = make_float4(acc[i][4], acc[i][5], acc[i][6], acc[i][7]);
        }
    }

    // ---- fused attn: es/ed per (row, head); this thread's 8 cols sit in head tx/4 ----
    const int head = tx >> 2;
    const int seg = (tx & 3) * 8;       // column offset within head
    float sA[8], dA[8];
    *(float4*)(sA)     = *(const float4*)(a_s + head * 32 + seg);
    *(float4*)(sA + 4) = *(const float4*)(a_s + head * 32 + seg + 4);
    *(float4*)(dA)     = *(const float4*)(a_d + head * 32 + seg);
    *(float4*)(dA + 4) = *(const float4*)(a_d + head * 32 + seg + 4);
#pragma unroll
    for (int i = 0; i < 8; i++) {
        float s = 0.f, d = 0.f;
#pragma unroll
        for (int j = 0; j < 8; j++) {
            s += acc[i][j] * sA[j];
            d += acc[i][j] * dA[j];
        }
        // reduce across the 4 tx-neighbors (lane bits 0-1 == tx bits 0-1)
        s += __shfl_xor_sync(0xffffffff, s, 1);
        d += __shfl_xor_sync(0xffffffff, d, 1);
        s += __shfl_xor_sync(0xffffffff, s, 2);
        d += __shfl_xor_sync(0xffffffff, d, 2);
        int r = rowBase + ty * 8 + i;
        if ((tx & 3) == 0 && r < M) {
            g_es[r * 4 + head] = s;
            g_ed[r * 4 + head] = d;
        }
    }
}

// ---------------- layer-3 GEMM + fused attn (H=1, C=16) ----------------
__global__ __launch_bounds__(256) void k_gemm16(
    const float* __restrict__ A, const float* __restrict__ W,
    float* __restrict__ C, int M,
    const float* __restrict__ a_s, const float* __restrict__ a_d)
{
    __shared__ float Ws[128 * 16];
    int tid = threadIdx.x;
    for (int i = tid * 4; i < 2048; i += 1024)
        *(float4*)&Ws[i] = *(const float4*)(W + i);
    __syncthreads();
    int row = blockIdx.x * 64 + (tid >> 2);
    int c4 = (tid & 3) * 4;
    if (row >= M) return;
    const float* Ap = A + (long)row * 128;
    float4 acc = make_float4(0, 0, 0, 0);
#pragma unroll 8
    for (int k = 0; k < 128; k += 4) {
        float4 a = *(const float4*)(Ap + k);
#pragma unroll
        for (int kk = 0; kk < 4; kk++) {
            float av = (&a.x)[kk];
            float4 w = *(const float4*)&Ws[(k + kk) * 16 + c4];
            acc.x += av * w.x; acc.y += av * w.y;
            acc.z += av * w.z; acc.w += av * w.w;
        }
    }
    *(float4*)(C + (long)row * 16 + c4) = acc;

    // fused attn: dot 4-wide, reduce over the 4 lanes covering this row
    float4 u = *(const float4*)(a_s + c4);
    float4 v = *(const float4*)(a_d + c4);
    float s = acc.x * u.x + acc.y * u.y + acc.z * u.z + acc.w * u.w;
    float d = acc.x * v.x + acc.y * v.y + acc.z * v.z + acc.w * v.w;
    s += __shfl_xor_sync(0xffffffff, s, 1);
    d += __shfl_xor_sync(0xffffffff, d, 1);
    s += __shfl_xor_sync(0xffffffff, s, 2);
    d += __shfl_xor_sync(0xffffffff, d, 2);
    if ((tid & 3) == 0) { g_es[row] = s; g_ed[row] = d; }
}

// ---------------- fused gather: softmax-weighted aggregation, warp per dst ----
template<bool RELU>
__global__ void k_gather128(const float* __restrict__ h, float* __restrict__ o,
                            const float* __restrict__ bias)
{
    int w = (blockIdx.x * blockDim.x + threadIdx.x) >> 5;
    int lane = threadIdx.x & 31;
    if (w >= NN) return;
    int head = lane >> 3;
    float edh = g_ed[w * 4 + head];
    float denom = 0.f;
    float4 acc = make_float4(0, 0, 0, 0);

    // self loop
    {
        float v = g_es[w * 4 + head] + edh;
        v = (v > 0.f) ? v : NEG * v;
        float p = __expf(v);
        denom += p;
        float4 hv = *(const float4*)(h + (long)w * 128 + lane * 4);
        acc.x += p * hv.x; acc.y += p * hv.y; acc.z += p * hv.z; acc.w += p * hv.w;
    }
    int j = g_rowptr[w], end = g_rowptr[w + 1];
    for (; j + 2 <= end; j += 2) {
        int s0 = g_csrc[j], s1 = g_csrc[j + 1];
        float v0 = g_es[s0 * 4 + head] + edh;
        float v1 = g_es[s1 * 4 + head] + edh;
        float4 h0 = *(const float4*)(h + (long)s0 * 128 + lane * 4);
        float4 h1 = *(const float4*)(h + (long)s1 * 128 + lane * 4);
        v0 = (v0 > 0.f) ? v0 : NEG * v0;
        v1 = (v1 > 0.f) ? v1 : NEG * v1;
        float p0 = __expf(v0), p1 = __expf(v1);
        denom += p0 + p1;
        acc.x += p0 * h0.x + p1 * h1.x;
        acc.y += p0 * h0.y + p1 * h1.y;
        acc.z += p0 * h0.z + p1 * h1.z;
        acc.w += p0 * h0.w + p1 * h1.w;
    }
    if (j < end) {
        int s = g_csrc[j];
        float v = g_es[s * 4 + head] + edh;
        v = (v > 0.f) ? v : NEG * v;
        float p = __expf(v);
        denom += p;
        float4 hv = *(const float4*)(h + (long)s * 128 + lane * 4);
        acc.x += p * hv.x; acc.y += p * hv.y; acc.z += p * hv.z; acc.w += p * hv.w;
    }
    float inv = 1.f / (denom + 1e-16f);
    float4 b = *(const float4*)(bias + lane * 4);
    float4 r;
    r.x = acc.x * inv + b.x; r.y = acc.y * inv + b.y;
    r.z = acc.z * inv + b.z; r.w = acc.w * inv + b.w;
    if (RELU) {
        r.x = fmaxf(r.x, 0.f); r.y = fmaxf(r.y, 0.f);
        r.z = fmaxf(r.z, 0.f); r.w = fmaxf(r.w, 0.f);
    }
    *(float4*)(o + (long)w * 128 + lane * 4) = r;
}

// ---------------- fused gather (F=16, H=1): 4 lanes per dst ----------------
__global__ void k_gather16(const float* __restrict__ h, float* __restrict__ o,
                           const float* __restrict__ bias)
{
    int g = blockIdx.x * blockDim.x + threadIdx.x;
    int n = g >> 2, q = g & 3;
    if (n >= NN) return;
    float edh = g_ed[n];
    float denom = 0.f;
    float4 acc = make_float4(0, 0, 0, 0);
    {
        float v = g_es[n] + edh;
        v = (v > 0.f) ? v : NEG * v;
        float p = __expf(v);
        denom += p;
        float4 hv = *(const float4*)(h + (long)n * 16 + q * 4);
        acc.x += p * hv.x; acc.y += p * hv.y; acc.z += p * hv.z; acc.w += p * hv.w;
    }
    int j = g_rowptr[n], end = g_rowptr[n + 1];
    for (; j + 2 <= end; j += 2) {
        int s0 = g_csrc[j], s1 = g_csrc[j + 1];
        float v0 = g_es[s0] + edh;
        float v1 = g_es[s1] + edh;
        float4 h0 = *(const float4*)(h + (long)s0 * 16 + q * 4);
        float4 h1 = *(const float4*)(h + (long)s1 * 16 + q * 4);
        v0 = (v0 > 0.f) ? v0 : NEG * v0;
        v1 = (v1 > 0.f) ? v1 : NEG * v1;
        float p0 = __expf(v0), p1 = __expf(v1);
        denom += p0 + p1;
        acc.x += p0 * h0.x + p1 * h1.x;
        acc.y += p0 * h0.y + p1 * h1.y;
        acc.z += p0 * h0.z + p1 * h1.z;
        acc.w += p0 * h0.w + p1 * h1.w;
    }
    if (j < end) {
        int s = g_csrc[j];
        float v = g_es[s] + edh;
        v = (v > 0.f) ? v : NEG * v;
        float p = __expf(v);
        denom += p;
        float4 hv = *(const float4*)(h + (long)s * 16 + q * 4);
        acc.x += p * hv.x; acc.y += p * hv.y; acc.z += p * hv.z; acc.w += p * hv.w;
    }
    float inv = 1.f / (denom + 1e-16f);
    float4 b = *(const float4*)(bias + q * 4);
    float4 r;
    r.x = acc.x * inv + b.x; r.y = acc.y * inv + b.y;
    r.z = acc.z * inv + b.z; r.w = acc.w * inv + b.w;
    *(float4*)(o + (long)n * 16 + q * 4) = r;
}

// ---------------- launch ----------------
extern "C" void kernel_launch(void* const* d_in, const int* in_sizes, int n_in,
                              void* d_out, int out_size)
{
    const float* x   = (const float*)d_in[0];
    const int*   ei  = (const int*)d_in[1];
    const float* W1  = (const float*)d_in[2];
    const float* as1 = (const float*)d_in[3];
    const float* ad1 = (const float*)d_in[4];
    const float* b1  = (const float*)d_in[5];
    const float* W2  = (const float*)d_in[6];
    const float* as2 = (const float*)d_in[7];
    const float* ad2 = (const float*)d_in[8];
    const float* b2  = (const float*)d_in[9];
    const float* W3  = (const float*)d_in[10];
    const float* as3 = (const float*)d_in[11];
    const float* ad3 = (const float*)d_in[12];
    const float* b3  = (const float*)d_in[13];
    float* out = (float*)d_out;

    float *bufA, *bufB, *h3;
    cudaGetSymbolAddress((void**)&bufA, g_bufA);
    cudaGetSymbolAddress((void**)&bufB, g_bufB);
    cudaGetSymbolAddress((void**)&h3,   g_h3);

    const int T = 256;
    // ---- CSR build (once; shared by all 3 layers) ----
    k_prep<<<(NN + T - 1) / T, T>>>(ei);
    k_detect<<<1, 64>>>(ei);
    k_convert<<<(NE + T - 1) / T, T>>>(ei);
    k_scan1<<<NSCANB, SCAN_B>>>();
    k_scan3<<<(NN + T - 1) / T, T>>>();
    k_fill<<<(NE + T - 1) / T, T>>>();

    const int gGemm = (NN + 127) / 128;
    const int gWarp = (NN * 32 + T - 1) / T;     // warp per node
    const int gQuad = (NN * 4 + T - 1) / T;      // 4 lanes per node

    // ---------- layer 1 ----------
    k_gemm128<<<gGemm, T>>>(x, W1, bufA, NN, as1, ad1);
    k_gather128<true><<<gWarp, T>>>(bufA, bufB, b1);

    // ---------- layer 2 ----------
    k_gemm128<<<gGemm, T>>>(bufB, W2, bufA, NN, as2, ad2);
    k_gather128<true><<<gWarp, T>>>(bufA, bufB, b2);

    // ---------- layer 3 ----------
    k_gemm16<<<(NN + 63) / 64, T>>>(bufB, W3, h3, NN, as3, ad3);
    k_gather16<<<gQuad, T>>>(h3, out, b3);
}

// round 8
// speedup vs baseline: 3.2306x; 1.3390x over previous
#include <cuda_runtime.h>
#include <cuda_bf16.h>
#include <cstdint>

#define NN   50000
#define NE   800000
#define FDIM 128
#define FOUT 16
#define NEG  0.2f
#define SCAN_B 512
#define NSCANB ((NN + SCAN_B - 1) / SCAN_B)   // 98

// gemm smem layout (bytes): A row stride = 136 bf16 = 272 B
#define SA_HI 0
#define SA_LO 34816
#define SB_HI 69632
#define SB_LO 102400
#define GEMM_SMEM 135168

// ---------------- scratch ----------------
__device__ __align__(16) float g_bufA[NN * FDIM];
__device__ __align__(16) float g_bufB[NN * FDIM];
__device__ __align__(16) float g_h3[NN * FOUT];
__device__ __align__(16) float g_es[NN * 4];
__device__ __align__(16) float g_ed[NN * 4];
__device__ __align__(16) uint32_t g_wfHi[8192];   // W fragments, hi bf16
__device__ __align__(16) uint32_t g_wfLo[8192];   // W fragments, lo bf16
__device__ int g_src[NE];
__device__ int g_dst[NE];
__device__ int g_deg[NN];
__device__ int g_rowptr[NN + 1];
__device__ int g_cursor[NN];
__device__ int g_csrc[NE];
__device__ int g_bsum[128];
__device__ int g_is32;

// pack two fp32 into bf16x2 hi word + bf16x2 residual word
__device__ __forceinline__ void split2(float x, float y, uint32_t& h, uint32_t& l) {
    __nv_bfloat16 hx = __float2bfloat16(x), hy = __float2bfloat16(y);
    __nv_bfloat16 lx = __float2bfloat16(x - __bfloat162float(hx));
    __nv_bfloat16 ly = __float2bfloat16(y - __bfloat162float(hy));
    h = ((uint32_t)__bfloat16_as_ushort(hy) << 16) | __bfloat16_as_ushort(hx);
    l = ((uint32_t)__bfloat16_as_ushort(ly) << 16) | __bfloat16_as_ushort(lx);
}

__device__ __forceinline__ void mma_bf16(float* c, const uint32_t* a, uint32_t b0, uint32_t b1) {
    asm volatile(
        "mma.sync.aligned.m16n8k16.row.col.f32.bf16.bf16.f32 "
        "{%0,%1,%2,%3}, {%4,%5,%6,%7}, {%8,%9}, {%0,%1,%2,%3};"
        : "+f"(c[0]), "+f"(c[1]), "+f"(c[2]), "+f"(c[3])
        : "r"(a[0]), "r"(a[1]), "r"(a[2]), "r"(a[3]), "r"(b0), "r"(b1));
}

// ---------------- detect dtype + zero degree ----------------
__global__ void k_prep(const int* __restrict__ ei) {
    int i = blockIdx.x * blockDim.x + threadIdx.x;
    if (i == 0) g_is32 = 0;
    if (i < NN) g_deg[i] = 0;
}
__global__ void k_detect(const int* __restrict__ ei) {
    if (ei[2 * threadIdx.x + 1] != 0) atomicExch(&g_is32, 1);
}

__global__ void k_convert(const int* __restrict__ ei) {
    int e = blockIdx.x * blockDim.x + threadIdx.x;
    if (e >= NE) return;
    int s, d;
    if (g_is32) {
        s = ei[e]; d = ei[NE + e];
    } else {
        const long long* ell = (const long long*)ei;
        s = (int)ell[e]; d = (int)ell[NE + e];
    }
    g_src[e] = s;
    g_dst[e] = d;
    atomicAdd(&g_deg[d], 1);
}

// ---------------- exclusive scan ----------------
__global__ void k_scan1() {
    __shared__ int sm[SCAN_B];
    int i = blockIdx.x * SCAN_B + threadIdx.x;
    int v = (i < NN) ? g_deg[i] : 0;
    sm[threadIdx.x] = v;
    __syncthreads();
#pragma unroll
    for (int off = 1; off < SCAN_B; off <<= 1) {
        int t = (threadIdx.x >= off) ? sm[threadIdx.x - off] : 0;
        __syncthreads();
        sm[threadIdx.x] += t;
        __syncthreads();
    }
    if (i < NN) g_rowptr[i] = sm[threadIdx.x] - v;
    if (threadIdx.x == SCAN_B - 1) g_bsum[blockIdx.x] = sm[SCAN_B - 1];
}

__global__ void k_scan3() {
    __shared__ int pre[NSCANB];
    if (threadIdx.x < NSCANB) pre[threadIdx.x] = g_bsum[threadIdx.x];
    __syncthreads();
    if (threadIdx.x == 0) {
        int run = 0;
#pragma unroll 1
        for (int b = 0; b < NSCANB; b++) { int t = pre[b]; pre[b] = run; run += t; }
    }
    __syncthreads();
    int i = blockIdx.x * blockDim.x + threadIdx.x;
    if (i < NN) {
        int v = g_rowptr[i] + pre[i / SCAN_B];
        g_rowptr[i] = v;
        g_cursor[i] = v;
    }
    if (i == 0) g_rowptr[NN] = NE;
}

__global__ void k_fill() {
    int e = blockIdx.x * blockDim.x + threadIdx.x;
    if (e >= NE) return;
    int pos = atomicAdd(&g_cursor[g_dst[e]], 1);
    g_csrc[pos] = g_src[e];
}

// ---- pre-pack W [128k x 128n] into mma B-fragment order, split hi/lo ----
// word index = ((ks*16 + nb)*32 + lane)*2 + reg
__global__ void k_wfrag(const float* __restrict__ W) {
    int i = blockIdx.x * blockDim.x + threadIdx.x;
    if (i >= 8192) return;
    int reg = i & 1, lane = (i >> 1) & 31;
    int rest = i >> 6, nb = rest & 15, ks = rest >> 4;
    int g = lane >> 2, t = lane & 3;
    int n = nb * 8 + g;
    int k0 = ks * 16 + 2 * t + reg * 8;
    float w0 = W[k0 * 128 + n];
    float w1 = W[(k0 + 1) * 128 + n];
    uint32_t h, l;
    split2(w0, w1, h, l);
    g_wfHi[i] = h;
    g_wfLo[i] = l;
}

// ------- tensor-core GEMM: C[M,128] = A[M,128] @ W, bf16 split 3-product ----
// fused attn epilogue writes g_es/g_ed. Warp tile 32 rows x 64 cols.
__global__ __launch_bounds__(256, 1) void k_gemm128_mma(
    const float* __restrict__ A, float* __restrict__ C, int M,
    const float* __restrict__ a_s, const float* __restrict__ a_d)
{
    extern __shared__ char smem[];
    const int tid = threadIdx.x;
    const int rowBase = blockIdx.x * 128;

    // ---- load A tile, split into hi/lo bf16, padded rows (272B stride) ----
    {
        int r = tid & 127, half = tid >> 7;          // half: cols 0-63 / 64-127
        int gr = rowBase + r;
        const float* Ap = A + (long)gr * 128 + half * 64;
        char* ah = smem + SA_HI + r * 272 + half * 128;
        char* al = smem + SA_LO + r * 272 + half * 128;
#pragma unroll
        for (int q = 0; q < 8; q++) {
            float4 f0 = (gr < M) ? *(const float4*)(Ap + q * 8)     : make_float4(0,0,0,0);
            float4 f1 = (gr < M) ? *(const float4*)(Ap + q * 8 + 4) : make_float4(0,0,0,0);
            uint4 h, l;
            split2(f0.x, f0.y, h.x, l.x);
            split2(f0.z, f0.w, h.y, l.y);
            split2(f1.x, f1.y, h.z, l.z);
            split2(f1.z, f1.w, h.w, l.w);
            *(uint4*)(ah + q * 16) = h;
            *(uint4*)(al + q * 16) = l;
        }
    }
    // ---- copy pre-packed W fragments (flat) ----
    {
        const uint4* sH = (const uint4*)g_wfHi;
        const uint4* sL = (const uint4*)g_wfLo;
        uint4* dH = (uint4*)(smem + SB_HI);
        uint4* dL = (uint4*)(smem + SB_LO);
        for (int q = tid; q < 2048; q += 256) { dH[q] = sH[q]; dL[q] = sL[q]; }
    }
    __syncthreads();

    const int w = tid >> 5, lane = tid & 31;
    const int g = lane >> 2, t = lane & 3;
    const int mrow = (w >> 1) * 32;       // warp row base in tile
    const int nbB  = (w & 1) * 8;         // warp nblock base (8 nblocks = 64 cols)

    float acc[2][8][4];
#pragma unroll
    for (int mb = 0; mb < 2; mb++)
#pragma unroll
        for (int nb = 0; nb < 8; nb++)
#pragma unroll
            for (int q = 0; q < 4; q++) acc[mb][nb][q] = 0.f;

#pragma unroll
    for (int p = 0; p < 3; p++) {
        const char* Aarr = smem + (p == 2 ? SA_LO : SA_HI);
        const char* Barr = smem + (p == 1 ? SB_LO : SB_HI);
#pragma unroll
        for (int ks = 0; ks < 8; ks++) {
            uint32_t a[2][4];
#pragma unroll
            for (int mb = 0; mb < 2; mb++) {
                int r0 = mrow + mb * 16 + g;
                int kb = (ks * 16 + 2 * t) * 2;
                a[mb][0] = *(const uint32_t*)(Aarr + r0 * 272 + kb);
                a[mb][1] = *(const uint32_t*)(Aarr + (r0 + 8) * 272 + kb);
                a[mb][2] = *(const uint32_t*)(Aarr + r0 * 272 + kb + 16);
                a[mb][3] = *(const uint32_t*)(Aarr + (r0 + 8) * 272 + kb + 16);
            }
#pragma unroll
            for (int nb = 0; nb < 8; nb++) {
                uint2 b = *(const uint2*)(Barr + ((ks * 16 + nbB + nb) * 32 + lane) * 8);
                mma_bf16(acc[0][nb], a[0], b.x, b.y);
                mma_bf16(acc[1][nb], a[1], b.x, b.y);
            }
        }
    }

    // ---- epilogue: store C + fused es/ed ----
    float es[2][2][2], ed[2][2][2];   // [mb][rowhalf][head]
#pragma unroll
    for (int mb = 0; mb < 2; mb++)
#pragma unroll
        for (int rh = 0; rh < 2; rh++)
#pragma unroll
            for (int h = 0; h < 2; h++) { es[mb][rh][h] = 0.f; ed[mb][rh][h] = 0.f; }

#pragma unroll
    for (int mb = 0; mb < 2; mb++) {
        int r0 = rowBase + mrow + mb * 16 + g;
        int r1 = r0 + 8;
#pragma unroll
        for (int nb = 0; nb < 8; nb++) {
            int col = (w & 1) * 64 + nb * 8 + 2 * t;
            int h = nb >> 2;
            float c0 = acc[mb][nb][0], c1 = acc[mb][nb][1];
            float c2 = acc[mb][nb][2], c3 = acc[mb][nb][3];
            if (r0 < M) *(float2*)(C + (long)r0 * 128 + col) = make_float2(c0, c1);
            if (r1 < M) *(float2*)(C + (long)r1 * 128 + col) = make_float2(c2, c3);
            float as0 = a_s[col], as1 = a_s[col + 1];
            float ad0 = a_d[col], ad1 = a_d[col + 1];
            es[mb][0][h] += c0 * as0 + c1 * as1;
            es[mb][1][h] += c2 * as0 + c3 * as1;
            ed[mb][0][h] += c0 * ad0 + c1 * ad1;
            ed[mb][1][h] += c2 * ad0 + c3 * ad1;
        }
    }
    // reduce over the 4 t-lanes
#pragma unroll
    for (int mb = 0; mb < 2; mb++)
#pragma unroll
        for (int rh = 0; rh < 2; rh++)
#pragma unroll
            for (int h = 0; h < 2; h++) {
                float s = es[mb][rh][h], d = ed[mb][rh][h];
                s += __shfl_xor_sync(0xffffffff, s, 1);
                d += __shfl_xor_sync(0xffffffff, d, 1);
                s += __shfl_xor_sync(0xffffffff, s, 2);
                d += __shfl_xor_sync(0xffffffff, d, 2);
                if (t == 0) {
                    int row = rowBase + mrow + mb * 16 + rh * 8 + g;
                    if (row < M) {
                        int head = (w & 1) * 2 + h;
                        g_es[row * 4 + head] = s;
                        g_ed[row * 4 + head] = d;
                    }
                }
            }
}

// ---------------- layer-3 GEMM + fused attn (H=1, C=16) ----------------
__global__ __launch_bounds__(256) void k_gemm16(
    const float* __restrict__ A, const float* __restrict__ W,
    float* __restrict__ C, int M,
    const float* __restrict__ a_s, const float* __restrict__ a_d)
{
    __shared__ float Ws[128 * 16];
    int tid = threadIdx.x;
    for (int i = tid * 4; i < 2048; i += 1024)
        *(float4*)&Ws[i] = *(const float4*)(W + i);
    __syncthreads();
    int row = blockIdx.x * 64 + (tid >> 2);
    int c4 = (tid & 3) * 4;
    if (row >= M) return;
    const float* Ap = A + (long)row * 128;
    float4 acc = make_float4(0, 0, 0, 0);
#pragma unroll 8
    for (int k = 0; k < 128; k += 4) {
        float4 a = *(const float4*)(Ap + k);
#pragma unroll
        for (int kk = 0; kk < 4; kk++) {
            float av = (&a.x)[kk];
            float4 w = *(const float4*)&Ws[(k + kk) * 16 + c4];
            acc.x += av * w.x; acc.y += av * w.y;
            acc.z += av * w.z; acc.w += av * w.w;
        }
    }
    *(float4*)(C + (long)row * 16 + c4) = acc;

    float4 u = *(const float4*)(a_s + c4);
    float4 v = *(const float4*)(a_d + c4);
    float s = acc.x * u.x + acc.y * u.y + acc.z * u.z + acc.w * u.w;
    float d = acc.x * v.x + acc.y * v.y + acc.z * v.z + acc.w * v.w;
    s += __shfl_xor_sync(0xffffffff, s, 1);
    d += __shfl_xor_sync(0xffffffff, d, 1);
    s += __shfl_xor_sync(0xffffffff, s, 2);
    d += __shfl_xor_sync(0xffffffff, d, 2);
    if ((tid & 3) == 0) { g_es[row] = s; g_ed[row] = d; }
}

// ---------------- fused gather: softmax-weighted aggregation, warp per dst ----
template<bool RELU>
__global__ void k_gather128(const float* __restrict__ h, float* __restrict__ o,
                            const float* __restrict__ bias)
{
    int w = (blockIdx.x * blockDim.x + threadIdx.x) >> 5;
    int lane = threadIdx.x & 31;
    if (w >= NN) return;
    int head = lane >> 3;
    float edh = g_ed[w * 4 + head];
    float denom = 0.f;
    float4 acc = make_float4(0, 0, 0, 0);
    {
        float v = g_es[w * 4 + head] + edh;
        v = (v > 0.f) ? v : NEG * v;
        float p = __expf(v);
        denom += p;
        float4 hv = *(const float4*)(h + (long)w * 128 + lane * 4);
        acc.x += p * hv.x; acc.y += p * hv.y; acc.z += p * hv.z; acc.w += p * hv.w;
    }
    int j = g_rowptr[w], end = g_rowptr[w + 1];
    for (; j + 2 <= end; j += 2) {
        int s0 = g_csrc[j], s1 = g_csrc[j + 1];
        float v0 = g_es[s0 * 4 + head] + edh;
        float v1 = g_es[s1 * 4 + head] + edh;
        float4 h0 = *(const float4*)(h + (long)s0 * 128 + lane * 4);
        float4 h1 = *(const float4*)(h + (long)s1 * 128 + lane * 4);
        v0 = (v0 > 0.f) ? v0 : NEG * v0;
        v1 = (v1 > 0.f) ? v1 : NEG * v1;
        float p0 = __expf(v0), p1 = __expf(v1);
        denom += p0 + p1;
        acc.x += p0 * h0.x + p1 * h1.x;
        acc.y += p0 * h0.y + p1 * h1.y;
        acc.z += p0 * h0.z + p1 * h1.z;
        acc.w += p0 * h0.w + p1 * h1.w;
    }
    if (j < end) {
        int s = g_csrc[j];
        float v = g_es[s * 4 + head] + edh;
        v = (v > 0.f) ? v : NEG * v;
        float p = __expf(v);
        denom += p;
        float4 hv = *(const float4*)(h + (long)s * 128 + lane * 4);
        acc.x += p * hv.x; acc.y += p * hv.y; acc.z += p * hv.z; acc.w += p * hv.w;
    }
    float inv = 1.f / (denom + 1e-16f);
    float4 b = *(const float4*)(bias + lane * 4);
    float4 r;
    r.x = acc.x * inv + b.x; r.y = acc.y * inv + b.y;
    r.z = acc.z * inv + b.z; r.w = acc.w * inv + b.w;
    if (RELU) {
        r.x = fmaxf(r.x, 0.f); r.y = fmaxf(r.y, 0.f);
        r.z = fmaxf(r.z, 0.f); r.w = fmaxf(r.w, 0.f);
    }
    *(float4*)(o + (long)w * 128 + lane * 4) = r;
}

// ---------------- fused gather (F=16, H=1): 4 lanes per dst ----------------
__global__ void k_gather16(const float* __restrict__ h, float* __restrict__ o,
                           const float* __restrict__ bias)
{
    int g = blockIdx.x * blockDim.x + threadIdx.x;
    int n = g >> 2, q = g & 3;
    if (n >= NN) return;
    float edh = g_ed[n];
    float denom = 0.f;
    float4 acc = make_float4(0, 0, 0, 0);
    {
        float v = g_es[n] + edh;
        v = (v > 0.f) ? v : NEG * v;
        float p = __expf(v);
        denom += p;
        float4 hv = *(const float4*)(h + (long)n * 16 + q * 4);
        acc.x += p * hv.x; acc.y += p * hv.y; acc.z += p * hv.z; acc.w += p * hv.w;
    }
    int j = g_rowptr[n], end = g_rowptr[n + 1];
    for (; j + 2 <= end; j += 2) {
        int s0 = g_csrc[j], s1 = g_csrc[j + 1];
        float v0 = g_es[s0] + edh;
        float v1 = g_es[s1] + edh;
        float4 h0 = *(const float4*)(h + (long)s0 * 16 + q * 4);
        float4 h1 = *(const float4*)(h + (long)s1 * 16 + q * 4);
        v0 = (v0 > 0.f) ? v0 : NEG * v0;
        v1 = (v1 > 0.f) ? v1 : NEG * v1;
        float p0 = __expf(v0), p1 = __expf(v1);
        denom += p0 + p1;
        acc.x += p0 * h0.x + p1 * h1.x;
        acc.y += p0 * h0.y + p1 * h1.y;
        acc.z += p0 * h0.z + p1 * h1.z;
        acc.w += p0 * h0.w + p1 * h1.w;
    }
    if (j < end) {
        int s = g_csrc[j];
        float v = g_es[s] + edh;
        v = (v > 0.f) ? v : NEG * v;
        float p = __expf(v);
        denom += p;
        float4 hv = *(const float4*)(h + (long)s * 16 + q * 4);
        acc.x += p * hv.x; acc.y += p * hv.y; acc.z += p * hv.z; acc.w += p * hv.w;
    }
    float inv = 1.f / (denom + 1e-16f);
    float4 b = *(const float4*)(bias + q * 4);
    float4 r;
    r.x = acc.x * inv + b.x; r.y = acc.y * inv + b.y;
    r.z = acc.z * inv + b.z; r.w = acc.w * inv + b.w;
    *(float4*)(o + (long)n * 16 + q * 4) = r;
}

// ---------------- launch ----------------
extern "C" void kernel_launch(void* const* d_in, const int* in_sizes, int n_in,
                              void* d_out, int out_size)
{
    const float* x   = (const float*)d_in[0];
    const int*   ei  = (const int*)d_in[1];
    const float* W1  = (const float*)d_in[2];
    const float* as1 = (const float*)d_in[3];
    const float* ad1 = (const float*)d_in[4];
    const float* b1  = (const float*)d_in[5];
    const float* W2  = (const float*)d_in[6];
    const float* as2 = (const float*)d_in[7];
    const float* ad2 = (const float*)d_in[8];
    const float* b2  = (const float*)d_in[9];
    const float* W3  = (const float*)d_in[10];
    const float* as3 = (const float*)d_in[11];
    const float* ad3 = (const float*)d_in[12];
    const float* b3  = (const float*)d_in[13];
    float* out = (float*)d_out;

    float *bufA, *bufB, *h3;
    cudaGetSymbolAddress((void**)&bufA, g_bufA);
    cudaGetSymbolAddress((void**)&bufB, g_bufB);
    cudaGetSymbolAddress((void**)&h3,   g_h3);

    cudaFuncSetAttribute(k_gemm128_mma,
                         cudaFuncAttributeMaxDynamicSharedMemorySize, GEMM_SMEM);

    const int T = 256;
    // ---- CSR build (once; shared by all 3 layers) ----
    k_prep<<<(NN + T - 1) / T, T>>>(ei);
    k_detect<<<1, 64>>>(ei);
    k_convert<<<(NE + T - 1) / T, T>>>(ei);
    k_scan1<<<NSCANB, SCAN_B>>>();
    k_scan3<<<(NN + T - 1) / T, T>>>();
    k_fill<<<(NE + T - 1) / T, T>>>();

    const int gGemm = (NN + 127) / 128;
    const int gWarp = (NN * 32 + T - 1) / T;
    const int gQuad = (NN * 4 + T - 1) / T;

    // ---------- layer 1 ----------
    k_wfrag<<<32, 256>>>(W1);
    k_gemm128_mma<<<gGemm, T, GEMM_SMEM>>>(x, bufA, NN, as1, ad1);
    k_gather128<true><<<gWarp, T>>>(bufA, bufB, b1);

    // ---------- layer 2 ----------
    k_wfrag<<<32, 256>>>(W2);
    k_gemm128_mma<<<gGemm, T, GEMM_SMEM>>>(bufB, bufA, NN, as2, ad2);
    k_gather128<true><<<gWarp, T>>>(bufA, bufB, b2);

    // ---------- layer 3 ----------
    k_gemm16<<<(NN + 63) / 64, T>>>(bufB, W3, h3, NN, as3, ad3);
    k_gather16<<<gQuad, T>>>(h3, out, b3);
}

// round 11
// speedup vs baseline: 3.2732x; 1.0132x over previous
#include <cuda_runtime.h>
#include <cuda_bf16.h>
#include <cstdint>

#define NN   50000
#define NE   800000
#define FDIM 128
#define FOUT 16
#define NEG  0.2f
#define SCAN_B 512
#define NSCANB ((NN + SCAN_B - 1) / SCAN_B)   // 98

// gemm smem layout (bytes): A row stride = 136 bf16 = 272 B
#define SA_HI 0
#define SA_LO 34816
#define SB_HI 69632
#define SB_LO 102400
#define GEMM_SMEM 135168

// ---------------- scratch ----------------
__device__ __align__(16) float g_bufA[NN * FDIM];
__device__ __align__(16) float g_bufB[NN * FDIM];
__device__ __align__(16) float g_h3[NN * FOUT];
__device__ __align__(16) float g_es[NN * 4];
__device__ __align__(16) float g_ed[NN * 4];
__device__ __align__(16) uint32_t g_wfHi[16384];   // W fragments (2 layers), hi bf16
__device__ __align__(16) uint32_t g_wfLo[16384];   // W fragments (2 layers), lo bf16
__device__ int g_src[NE];
__device__ int g_dst[NE];
__device__ int g_deg[NN];
__device__ int g_rowptr[NN + 1];
__device__ int g_cursor[NN];
__device__ int g_csrc[NE];
__device__ int g_bsum[128];
__device__ int g_is32;

// pack two fp32 into bf16x2 hi word + bf16x2 residual word
__device__ __forceinline__ void split2(float x, float y, uint32_t& h, uint32_t& l) {
    __nv_bfloat16 hx = __float2bfloat16(x), hy = __float2bfloat16(y);
    __nv_bfloat16 lx = __float2bfloat16(x - __bfloat162float(hx));
    __nv_bfloat16 ly = __float2bfloat16(y - __bfloat162float(hy));
    h = ((uint32_t)__bfloat16_as_ushort(hy) << 16) | __bfloat16_as_ushort(hx);
    l = ((uint32_t)__bfloat16_as_ushort(ly) << 16) | __bfloat16_as_ushort(lx);
}

__device__ __forceinline__ void mma_bf16(float* c, const uint32_t* a, uint32_t b0, uint32_t b1) {
    asm volatile(
        "mma.sync.aligned.m16n8k16.row.col.f32.bf16.bf16.f32 "
        "{%0,%1,%2,%3}, {%4,%5,%6,%7}, {%8,%9}, {%0,%1,%2,%3};"
        : "+f"(c[0]), "+f"(c[1]), "+f"(c[2]), "+f"(c[3])
        : "r"(a[0]), "r"(a[1]), "r"(a[2]), "r"(a[3]), "r"(b0), "r"(b1));
}

// ---- setup: zero degree + dtype detect + pack W1/W2 mma fragments ----
// frag word index (within slot) = ((ks*16 + nb)*32 + lane)*2 + reg
__global__ void k_setup(const int* __restrict__ ei,
                        const float* __restrict__ W1, const float* __restrict__ W2)
{
    int i = blockIdx.x * blockDim.x + threadIdx.x;
    if (i < NN) g_deg[i] = 0;
    if (i == 0) {
        int nz = 0;
#pragma unroll
        for (int t = 0; t < 16; t++) nz |= ei[2 * t + 1];
        g_is32 = (nz != 0);
    }
    if (i < 16384) {
        const float* W = (i < 8192) ? W1 : W2;
        int idx = i & 8191;
        int reg = idx & 1, lane = (idx >> 1) & 31;
        int rest = idx >> 6, nb = rest & 15, ks = rest >> 4;
        int g = lane >> 2, t = lane & 3;
        int n = nb * 8 + g;
        int k0 = ks * 16 + 2 * t + reg * 8;
        float w0 = W[k0 * 128 + n];
        float w1 = W[(k0 + 1) * 128 + n];
        uint32_t h, l;
        split2(w0, w1, h, l);
        g_wfHi[i] = h;
        g_wfLo[i] = l;
    }
}

__global__ void k_convert(const int* __restrict__ ei) {
    int e = blockIdx.x * blockDim.x + threadIdx.x;
    if (e >= NE) return;
    int s, d;
    if (g_is32) {
        s = ei[e]; d = ei[NE + e];
    } else {
        const long long* ell = (const long long*)ei;
        s = (int)ell[e]; d = (int)ell[NE + e];
    }
    g_src[e] = s;
    g_dst[e] = d;
    atomicAdd(&g_deg[d], 1);
}

// ---------------- exclusive scan ----------------
__global__ void k_scan1() {
    __shared__ int sm[SCAN_B];
    int i = blockIdx.x * SCAN_B + threadIdx.x;
    int v = (i < NN) ? g_deg[i] : 0;
    sm[threadIdx.x] = v;
    __syncthreads();
#pragma unroll
    for (int off = 1; off < SCAN_B; off <<= 1) {
        int t = (threadIdx.x >= off) ? sm[threadIdx.x - off] : 0;
        __syncthreads();
        sm[threadIdx.x] += t;
        __syncthreads();
    }
    if (i < NN) g_rowptr[i] = sm[threadIdx.x] - v;
    if (threadIdx.x == SCAN_B - 1) g_bsum[blockIdx.x] = sm[SCAN_B - 1];
}

__global__ void k_scan3() {
    __shared__ int pre[NSCANB];
    if (threadIdx.x < NSCANB) pre[threadIdx.x] = g_bsum[threadIdx.x];
    __syncthreads();
    if (threadIdx.x == 0) {
        int run = 0;
#pragma unroll 1
        for (int b = 0; b < NSCANB; b++) { int t = pre[b]; pre[b] = run; run += t; }
    }
    __syncthreads();
    int i = blockIdx.x * blockDim.x + threadIdx.x;
    if (i < NN) {
        int v = g_rowptr[i] + pre[i / SCAN_B];
        g_rowptr[i] = v;
        g_cursor[i] = v;
    }
    if (i == 0) g_rowptr[NN] = NE;
}

__global__ void k_fill() {
    int e = blockIdx.x * blockDim.x + threadIdx.x;
    if (e >= NE) return;
    int pos = atomicAdd(&g_cursor[g_dst[e]], 1);
    g_csrc[pos] = g_src[e];
}

// ------- tensor-core GEMM: C[M,128] = A[M,128] @ W, bf16 split 3-product ----
__global__ __launch_bounds__(256, 1) void k_gemm128_mma(
    const float* __restrict__ A, float* __restrict__ C, int M,
    const float* __restrict__ a_s, const float* __restrict__ a_d, int slot)
{
    extern __shared__ char smem[];
    const int tid = threadIdx.x;
    const int rowBase = blockIdx.x * 128;

    // ---- load A tile, split into hi/lo bf16, padded rows (272B stride) ----
    {
        int r = tid & 127, half = tid >> 7;
        int gr = rowBase + r;
        const float* Ap = A + (long)gr * 128 + half * 64;
        char* ah = smem + SA_HI + r * 272 + half * 128;
        char* al = smem + SA_LO + r * 272 + half * 128;
#pragma unroll
        for (int q = 0; q < 8; q++) {
            float4 f0 = (gr < M) ? *(const float4*)(Ap + q * 8)     : make_float4(0,0,0,0);
            float4 f1 = (gr < M) ? *(const float4*)(Ap + q * 8 + 4) : make_float4(0,0,0,0);
            uint4 h, l;
            split2(f0.x, f0.y, h.x, l.x);
            split2(f0.z, f0.w, h.y, l.y);
            split2(f1.x, f1.y, h.z, l.z);
            split2(f1.z, f1.w, h.w, l.w);
            *(uint4*)(ah + q * 16) = h;
            *(uint4*)(al + q * 16) = l;
        }
    }
    // ---- copy pre-packed W fragments (flat) ----
    {
        const uint4* sH = (const uint4*)(g_wfHi + slot * 8192);
        const uint4* sL = (const uint4*)(g_wfLo + slot * 8192);
        uint4* dH = (uint4*)(smem + SB_HI);
        uint4* dL = (uint4*)(smem + SB_LO);
        for (int q = tid; q < 2048; q += 256) { dH[q] = sH[q]; dL[q] = sL[q]; }
    }
    __syncthreads();

    const int w = tid >> 5, lane = tid & 31;
    const int g = lane >> 2, t = lane & 3;
    const int mrow = (w >> 1) * 32;
    const int nbB  = (w & 1) * 8;

    float acc[2][8][4];
#pragma unroll
    for (int mb = 0; mb < 2; mb++)
#pragma unroll
        for (int nb = 0; nb < 8; nb++)
#pragma unroll
            for (int q = 0; q < 4; q++) acc[mb][nb][q] = 0.f;

#pragma unroll
    for (int p = 0; p < 3; p++) {
        const char* Aarr = smem + (p == 2 ? SA_LO : SA_HI);
        const char* Barr = smem + (p == 1 ? SB_LO : SB_HI);
#pragma unroll
        for (int ks = 0; ks < 8; ks++) {
            uint32_t a[2][4];
#pragma unroll
            for (int mb = 0; mb < 2; mb++) {
                int r0 = mrow + mb * 16 + g;
                int kb = (ks * 16 + 2 * t) * 2;
                a[mb][0] = *(const uint32_t*)(Aarr + r0 * 272 + kb);
                a[mb][1] = *(const uint32_t*)(Aarr + (r0 + 8) * 272 + kb);
                a[mb][2] = *(const uint32_t*)(Aarr + r0 * 272 + kb + 16);
                a[mb][3] = *(const uint32_t*)(Aarr + (r0 + 8) * 272 + kb + 16);
            }
#pragma unroll
            for (int nb = 0; nb < 8; nb++) {
                uint2 b = *(const uint2*)(Barr + ((ks * 16 + nbB + nb) * 32 + lane) * 8);
                mma_bf16(acc[0][nb], a[0], b.x, b.y);
                mma_bf16(acc[1][nb], a[1], b.x, b.y);
            }
        }
    }

    // ---- epilogue: store C + fused es/ed ----
    float es[2][2][2], ed[2][2][2];
#pragma unroll
    for (int mb = 0; mb < 2; mb++)
#pragma unroll
        for (int rh = 0; rh < 2; rh++)
#pragma unroll
            for (int h = 0; h < 2; h++) { es[mb][rh][h] = 0.f; ed[mb][rh][h] = 0.f; }

#pragma unroll
    for (int mb = 0; mb < 2; mb++) {
        int r0 = rowBase + mrow + mb * 16 + g;
        int r1 = r0 + 8;
#pragma unroll
        for (int nb = 0; nb < 8; nb++) {
            int col = (w & 1) * 64 + nb * 8 + 2 * t;
            int h = nb >> 2;
            float c0 = acc[mb][nb][0], c1 = acc[mb][nb][1];
            float c2 = acc[mb][nb][2], c3 = acc[mb][nb][3];
            if (r0 < M) *(float2*)(C + (long)r0 * 128 + col) = make_float2(c0, c1);
            if (r1 < M) *(float2*)(C + (long)r1 * 128 + col) = make_float2(c2, c3);
            float as0 = a_s[col], as1 = a_s[col + 1];
            float ad0 = a_d[col], ad1 = a_d[col + 1];
            es[mb][0][h] += c0 * as0 + c1 * as1;
            es[mb][1][h] += c2 * as0 + c3 * as1;
            ed[mb][0][h] += c0 * ad0 + c1 * ad1;
            ed[mb][1][h] += c2 * ad0 + c3 * ad1;
        }
    }
#pragma unroll
    for (int mb = 0; mb < 2; mb++)
#pragma unroll
        for (int rh = 0; rh < 2; rh++)
#pragma unroll
            for (int h = 0; h < 2; h++) {
                float s = es[mb][rh][h], d = ed[mb][rh][h];
                s += __shfl_xor_sync(0xffffffff, s, 1);
                d += __shfl_xor_sync(0xffffffff, d, 1);
                s += __shfl_xor_sync(0xffffffff, s, 2);
                d += __shfl_xor_sync(0xffffffff, d, 2);
                if (t == 0) {
                    int row = rowBase + mrow + mb * 16 + rh * 8 + g;
                    if (row < M) {
                        int head = (w & 1) * 2 + h;
                        g_es[row * 4 + head] = s;
                        g_ed[row * 4 + head] = d;
                    }
                }
            }
}

// ---------------- layer-3 GEMM + fused attn (H=1, C=16) ----------------
__global__ __launch_bounds__(256) void k_gemm16(
    const float* __restrict__ A, const float* __restrict__ W,
    float* __restrict__ C, int M,
    const float* __restrict__ a_s, const float* __restrict__ a_d)
{
    __shared__ float Ws[128 * 16];
    int tid = threadIdx.x;
    for (int i = tid * 4; i < 2048; i += 1024)
        *(float4*)&Ws[i] = *(const float4*)(W + i);
    __syncthreads();
    int row = blockIdx.x * 64 + (tid >> 2);
    int c4 = (tid & 3) * 4;
    if (row >= M) return;
    const float* Ap = A + (long)row * 128;
    float4 acc = make_float4(0, 0, 0, 0);
#pragma unroll 8
    for (int k = 0; k < 128; k += 4) {
        float4 a = *(const float4*)(Ap + k);
#pragma unroll
        for (int kk = 0; kk < 4; kk++) {
            float av = (&a.x)[kk];
            float4 w = *(const float4*)&Ws[(k + kk) * 16 + c4];
            acc.x += av * w.x; acc.y += av * w.y;
            acc.z += av * w.z; acc.w += av * w.w;
        }
    }
    *(float4*)(C + (long)row * 16 + c4) = acc;

    float4 u = *(const float4*)(a_s + c4);
    float4 v = *(const float4*)(a_d + c4);
    float s = acc.x * u.x + acc.y * u.y + acc.z * u.z + acc.w * u.w;
    float d = acc.x * v.x + acc.y * v.y + acc.z * v.z + acc.w * v.w;
    s += __shfl_xor_sync(0xffffffff, s, 1);
    d += __shfl_xor_sync(0xffffffff, d, 1);
    s += __shfl_xor_sync(0xffffffff, s, 2);
    d += __shfl_xor_sync(0xffffffff, d, 2);
    if ((tid & 3) == 0) { g_es[row] = s; g_ed[row] = d; }
}

// ------- fused gather, warp per dst; csrc batched 32-at-a-time via shfl -----
template<bool RELU>
__global__ void k_gather128(const float* __restrict__ h, float* __restrict__ o,
                            const float* __restrict__ bias)
{
    int w = (blockIdx.x * blockDim.x + threadIdx.x) >> 5;
    int lane = threadIdx.x & 31;
    if (w >= NN) return;
    int head = lane >> 3;
    float edh = g_ed[w * 4 + head];
    float denom = 0.f;
    float4 acc = make_float4(0, 0, 0, 0);
    {
        float v = g_es[w * 4 + head] + edh;
        v = (v > 0.f) ? v : NEG * v;
        float p = __expf(v);
        denom += p;
        float4 hv = *(const float4*)(h + (long)w * 128 + lane * 4);
        acc.x += p * hv.x; acc.y += p * hv.y; acc.z += p * hv.z; acc.w += p * hv.w;
    }
    int j = g_rowptr[w], end = g_rowptr[w + 1];
    while (j < end) {
        int rem = end - j;
        int batch = rem < 32 ? rem : 32;
        int s_l = (lane < batch) ? g_csrc[j + lane] : 0;
        int t = 0;
        for (; t + 2 <= batch; t += 2) {
            int s0 = __shfl_sync(0xffffffff, s_l, t);
            int s1 = __shfl_sync(0xffffffff, s_l, t + 1);
            float v0 = g_es[s0 * 4 + head] + edh;
            float v1 = g_es[s1 * 4 + head] + edh;
            float4 h0 = *(const float4*)(h + (long)s0 * 128 + lane * 4);
            float4 h1 = *(const float4*)(h + (long)s1 * 128 + lane * 4);
            v0 = (v0 > 0.f) ? v0 : NEG * v0;
            v1 = (v1 > 0.f) ? v1 : NEG * v1;
            float p0 = __expf(v0), p1 = __expf(v1);
            denom += p0 + p1;
            acc.x += p0 * h0.x + p1 * h1.x;
            acc.y += p0 * h0.y + p1 * h1.y;
            acc.z += p0 * h0.z + p1 * h1.z;
            acc.w += p0 * h0.w + p1 * h1.w;
        }
        if (t < batch) {
            int s = __shfl_sync(0xffffffff, s_l, t);
            float v = g_es[s * 4 + head] + edh;
            v = (v > 0.f) ? v : NEG * v;
            float p = __expf(v);
            denom += p;
            float4 hv = *(const float4*)(h + (long)s * 128 + lane * 4);
            acc.x += p * hv.x; acc.y += p * hv.y; acc.z += p * hv.z; acc.w += p * hv.w;
        }
        j += batch;
    }
    float inv = 1.f / (denom + 1e-16f);
    float4 b = *(const float4*)(bias + lane * 4);
    float4 r;
    r.x = acc.x * inv + b.x; r.y = acc.y * inv + b.y;
    r.z = acc.z * inv + b.z; r.w = acc.w * inv + b.w;
    if (RELU) {
        r.x = fmaxf(r.x, 0.f); r.y = fmaxf(r.y, 0.f);
        r.z = fmaxf(r.z, 0.f); r.w = fmaxf(r.w, 0.f);
    }
    *(float4*)(o + (long)w * 128 + lane * 4) = r;
}

// ---- fused gather (F=16, H=1): quad per dst; csrc batched 4-at-a-time ------
__global__ void k_gather16(const float* __restrict__ h, float* __restrict__ o,
                           const float* __restrict__ bias)
{
    int g = blockIdx.x * blockDim.x + threadIdx.x;
    int n = g >> 2, q = g & 3;
    if (n >= NN) return;
    int lane = threadIdx.x & 31;
    int qbase = lane & 28;
    unsigned qmask = 0xFu << qbase;
    float edh = g_ed[n];
    float denom = 0.f;
    float4 acc = make_float4(0, 0, 0, 0);
    {
        float v = g_es[n] + edh;
        v = (v > 0.f) ? v : NEG * v;
        float p = __expf(v);
        denom += p;
        float4 hv = *(const float4*)(h + (long)n * 16 + q * 4);
        acc.x += p * hv.x; acc.y += p * hv.y; acc.z += p * hv.z; acc.w += p * hv.w;
    }
    int j = g_rowptr[n], end = g_rowptr[n + 1];
    while (j < end) {
        int rem = end - j;
        int batch = rem < 4 ? rem : 4;
        int s_l = (q < batch) ? g_csrc[j + q] : 0;
#pragma unroll 4
        for (int t = 0; t < batch; t++) {
            int s = __shfl_sync(qmask, s_l, qbase + t);
            float v = g_es[s] + edh;
            v = (v > 0.f) ? v : NEG * v;
            float p = __expf(v);
            denom += p;
            float4 hv = *(const float4*)(h + (long)s * 16 + q * 4);
            acc.x += p * hv.x; acc.y += p * hv.y; acc.z += p * hv.z; acc.w += p * hv.w;
        }
        j += batch;
    }
    float inv = 1.f / (denom + 1e-16f);
    float4 b = *(const float4*)(bias + q * 4);
    float4 r;
    r.x = acc.x * inv + b.x; r.y = acc.y * inv + b.y;
    r.z = acc.z * inv + b.z; r.w = acc.w * inv + b.w;
    *(float4*)(o + (long)n * 16 + q * 4) = r;
}

// ---------------- launch ----------------
extern "C" void kernel_launch(void* const* d_in, const int* in_sizes, int n_in,
                              void* d_out, int out_size)
{
    const float* x   = (const float*)d_in[0];
    const int*   ei  = (const int*)d_in[1];
    const float* W1  = (const float*)d_in[2];
    const float* as1 = (const float*)d_in[3];
    const float* ad1 = (const float*)d_in[4];
    const float* b1  = (const float*)d_in[5];
    const float* W2  = (const float*)d_in[6];
    const float* as2 = (const float*)d_in[7];
    const float* ad2 = (const float*)d_in[8];
    const float* b2  = (const float*)d_in[9];
    const float* W3  = (const float*)d_in[10];
    const float* as3 = (const float*)d_in[11];
    const float* ad3 = (const float*)d_in[12];
    const float* b3  = (const float*)d_in[13];
    float* out = (float*)d_out;

    float *bufA, *bufB, *h3;
    cudaGetSymbolAddress((void**)&bufA, g_bufA);
    cudaGetSymbolAddress((void**)&bufB, g_bufB);
    cudaGetSymbolAddress((void**)&h3,   g_h3);

    cudaFuncSetAttribute(k_gemm128_mma,
                         cudaFuncAttributeMaxDynamicSharedMemorySize, GEMM_SMEM);

    const int T = 256;
    const int gGemm = (NN + 127) / 128;
    const int gWarp = (NN * 32 + T - 1) / T;
    const int gQuad = (NN * 4 + T - 1) / T;

    // 1-3: setup + CSR phase 1 (gemm L1 only needs k_setup's wfrag)
    k_setup<<<(NN + T - 1) / T, T>>>(ei, W1, W2);
    k_convert<<<(NE + T - 1) / T, T>>>(ei);
    k_scan1<<<NSCANB, SCAN_B>>>();
    // 4: layer-1 GEMM (profiled slot)
    k_gemm128_mma<<<gGemm, T, GEMM_SMEM>>>(x, bufA, NN, as1, ad1, 0);
    // 5-6: finish CSR
    k_scan3<<<(NN + T - 1) / T, T>>>();
    k_fill<<<(NE + T - 1) / T, T>>>();
    // layer 1 aggregate
    k_gather128<true><<<gWarp, T>>>(bufA, bufB, b1);
    // layer 2
    k_gemm128_mma<<<gGemm, T, GEMM_SMEM>>>(bufB, bufA, NN, as2, ad2, 1);
    k_gather128<true><<<gWarp, T>>>(bufA, bufB, b2);
    // layer 3
    k_gemm16<<<(NN + 63) / 64, T>>>(bufB, W3, h3, NN, as3, ad3);
    k_gather16<<<gQuad, T>>>(h3, out, b3);
}